// round 1
// baseline (speedup 1.0000x reference)
#include <cuda_runtime.h>

#define Bb 512
#define Hh 1024
#define Nn 16384
#define Mm 128
#define Rr 4
#define Ss 3

// ---------------- scratch (device globals; no allocations allowed) ----------------
__device__ __align__(16) float g_k[Bb*Mm];
__device__ __align__(16) float g_e[Bb*Mm];
__device__ __align__(16) float g_a[Bb*Mm];
__device__ float g_beta[Bb], g_gate[Bb], g_slog[Bb*Ss], g_s[Bb*Ss];
__device__ float g_nk[Bb], g_nm[Nn], g_sum[Bb];
__device__ __align__(16) float g_t[(size_t)Bb*Nn];   // exp(beta*sim), unnormalized
__device__ __align__(16) float g_me[(size_t)Nn*Mm]; // ww^T @ e
__device__ __align__(16) float g_ma[(size_t)Nn*Mm]; // ww^T @ a

// ---------------- kernel 1: controller projections ----------------
// OUT(B, 389) = h(B,1024) @ Wcat^T + bias, with per-range activations.
// Block: 8 batches, 256 threads (8 warps). Warp computes one column j for all 8 b.
__global__ __launch_bounds__(256) void ctrl_kernel(
    const float* __restrict__ h,
    const float* __restrict__ kw, const float* __restrict__ kb,
    const float* __restrict__ bw, const float* __restrict__ bbv,
    const float* __restrict__ gw, const float* __restrict__ gb,
    const float* __restrict__ sw, const float* __restrict__ sb,
    const float* __restrict__ ew, const float* __restrict__ eb,
    const float* __restrict__ aw, const float* __restrict__ ab)
{
    __shared__ float h_s[8][Hh];
    int b0 = blockIdx.x * 8;
    for (int i = threadIdx.x; i < 8*Hh; i += 256)
        h_s[i >> 10][i & 1023] = h[(size_t)(b0 + (i >> 10))*Hh + (i & 1023)];
    __syncthreads();
    int warp = threadIdx.x >> 5, lane = threadIdx.x & 31;
    for (int j = warp; j < 3*Mm + 5; j += 8) {
        const float* wrow; float bias; int act;
        if (j < Mm)        { wrow = kw + (size_t)j*Hh;        bias = kb[j];      act = 0; }
        else if (j < 2*Mm) { wrow = ew + (size_t)(j-Mm)*Hh;   bias = eb[j-Mm];   act = 0; }
        else if (j < 3*Mm) { wrow = aw + (size_t)(j-2*Mm)*Hh; bias = ab[j-2*Mm]; act = 0; }
        else if (j == 384) { wrow = bw;                       bias = bbv[0];     act = 2; }
        else if (j == 385) { wrow = gw;                       bias = gb[0];      act = 0; }
        else               { wrow = sw + (size_t)(j-386)*Hh;  bias = sb[j-386];  act = 3; }
        float acc[8];
        #pragma unroll
        for (int q = 0; q < 8; q++) acc[q] = 0.f;
        for (int k = lane; k < Hh; k += 32) {
            float wv = __ldg(wrow + k);
            #pragma unroll
            for (int q = 0; q < 8; q++) acc[q] = fmaf(wv, h_s[q][k], acc[q]);
        }
        #pragma unroll
        for (int q = 0; q < 8; q++) {
            float v = acc[q];
            #pragma unroll
            for (int o = 16; o; o >>= 1) v += __shfl_down_sync(0xffffffffu, v, o);
            if (lane == 0) {
                v += bias;
                if (act == 0) v = fminf(fmaxf(v, 0.f), 1.f);
                else if (act == 2) v = fmaxf(v, 0.f);
                int b = b0 + q;
                if (j < Mm)        g_k[b*Mm + j] = v;
                else if (j < 2*Mm) g_e[b*Mm + (j-Mm)] = v;
                else if (j < 3*Mm) g_a[b*Mm + (j-2*Mm)] = v;
                else if (j == 384) g_beta[b] = v;
                else if (j == 385) g_gate[b] = v;
                else               g_slog[b*Ss + (j-386)] = v;
            }
        }
    }
}

// ---------------- kernel 2: norms, shift softmax, zero init ----------------
// blocks [0,2048): ||m[n]|| ; [2048,2112): ||k[b]||, softmax(s), g_sum=0 ; [2112,2240): zero r_t
__global__ __launch_bounds__(256) void prep_kernel(const float* __restrict__ m, float* __restrict__ r_out)
{
    int warp = threadIdx.x >> 5, lane = threadIdx.x & 31;
    int bidx = blockIdx.x;
    if (bidx < 2048) {
        int n = bidx*8 + warp;
        float4 v = *(const float4*)(m + (size_t)n*Mm + lane*4);
        float ss = v.x*v.x + v.y*v.y + v.z*v.z + v.w*v.w;
        #pragma unroll
        for (int o = 16; o; o >>= 1) ss += __shfl_down_sync(0xffffffffu, ss, o);
        if (lane == 0) g_nm[n] = sqrtf(ss);
    } else if (bidx < 2112) {
        int b = (bidx-2048)*8 + warp;
        float4 v = *(const float4*)(g_k + (size_t)b*Mm + lane*4);
        float ss = v.x*v.x + v.y*v.y + v.z*v.z + v.w*v.w;
        #pragma unroll
        for (int o = 16; o; o >>= 1) ss += __shfl_down_sync(0xffffffffu, ss, o);
        if (lane == 0) {
            g_nk[b] = sqrtf(ss);
            g_sum[b] = 0.f;
            float x0 = g_slog[b*Ss+0], x1 = g_slog[b*Ss+1], x2 = g_slog[b*Ss+2];
            float mx = fmaxf(x0, fmaxf(x1, x2));
            float e0 = expf(x0-mx), e1 = expf(x1-mx), e2 = expf(x2-mx);
            float it = 1.f / (e0+e1+e2);
            g_s[b*Ss+0] = e0*it; g_s[b*Ss+1] = e1*it; g_s[b*Ss+2] = e2*it;
        }
    } else {
        int base = (bidx-2112)*2048 + threadIdx.x*8;
        float4 z = make_float4(0.f,0.f,0.f,0.f);
        *(float4*)(r_out + base)     = z;
        *(float4*)(r_out + base + 4) = z;
    }
}

// ---------------- kernel 3: sim GEMM + exp + row sums ----------------
// C(B x N) = k(B,128) @ m^T; v = exp(beta * C/(|k||m|+eps)); store g_t; atomic row sums.
// tile 128b x 128n, 256 threads, 8x8 register tile. grid (128 n-tiles, 4 b-tiles)
__global__ __launch_bounds__(256) void sim_kernel(const float* __restrict__ m)
{
    __shared__ float a_s[16][128];
    __shared__ float b_s[16][128];
    __shared__ float ssum[128];
    int tid = threadIdx.x;
    int tx = tid & 15, ty = tid >> 4;
    int n0 = blockIdx.x * 128, b0 = blockIdx.y * 128;
    float acc[8][8];
    #pragma unroll
    for (int i = 0; i < 8; i++)
        #pragma unroll
        for (int j = 0; j < 8; j++) acc[i][j] = 0.f;
    int rl = tid >> 1, kk0 = (tid & 1) * 8;
    for (int kc = 0; kc < Mm; kc += 16) {
        float4 va0 = *(const float4*)(g_k + (size_t)(b0+rl)*Mm + kc + kk0);
        float4 va1 = *(const float4*)(g_k + (size_t)(b0+rl)*Mm + kc + kk0 + 4);
        float4 vb0 = *(const float4*)(m   + (size_t)(n0+rl)*Mm + kc + kk0);
        float4 vb1 = *(const float4*)(m   + (size_t)(n0+rl)*Mm + kc + kk0 + 4);
        a_s[kk0+0][rl]=va0.x; a_s[kk0+1][rl]=va0.y; a_s[kk0+2][rl]=va0.z; a_s[kk0+3][rl]=va0.w;
        a_s[kk0+4][rl]=va1.x; a_s[kk0+5][rl]=va1.y; a_s[kk0+6][rl]=va1.z; a_s[kk0+7][rl]=va1.w;
        b_s[kk0+0][rl]=vb0.x; b_s[kk0+1][rl]=vb0.y; b_s[kk0+2][rl]=vb0.z; b_s[kk0+3][rl]=vb0.w;
        b_s[kk0+4][rl]=vb1.x; b_s[kk0+5][rl]=vb1.y; b_s[kk0+6][rl]=vb1.z; b_s[kk0+7][rl]=vb1.w;
        __syncthreads();
        #pragma unroll
        for (int kk = 0; kk < 16; kk++) {
            float ar[8], br[8];
            *(float4*)(ar)   = *(const float4*)(&a_s[kk][ty*4]);
            *(float4*)(ar+4) = *(const float4*)(&a_s[kk][64 + ty*4]);
            *(float4*)(br)   = *(const float4*)(&b_s[kk][tx*4]);
            *(float4*)(br+4) = *(const float4*)(&b_s[kk][64 + tx*4]);
            #pragma unroll
            for (int i = 0; i < 8; i++)
                #pragma unroll
                for (int j = 0; j < 8; j++)
                    acc[i][j] = fmaf(ar[i], br[j], acc[i][j]);
        }
        __syncthreads();
    }
    if (tid < 128) ssum[tid] = 0.f;
    __syncthreads();
    #pragma unroll
    for (int i = 0; i < 8; i++) {
        int bl = (i < 4) ? (ty*4 + i) : (64 + ty*4 + (i-4));
        int bg = b0 + bl;
        float be = g_beta[bg];
        float nk = g_nk[bg];
        float rs = 0.f;
        #pragma unroll
        for (int jj = 0; jj < 2; jj++) {
            int nl = jj ? (64 + tx*4) : (tx*4);
            float4 vout; float* vp = (float*)&vout;
            #pragma unroll
            for (int q = 0; q < 4; q++) {
                int ng = n0 + nl + q;
                float sim = acc[i][jj*4+q] / (nk * g_nm[ng] + 1e-6f);
                float v = __expf(be * sim);
                vp[q] = v; rs += v;
            }
            *(float4*)(g_t + (size_t)bg*Nn + n0 + nl) = vout;
        }
        atomicAdd(&ssum[bl], rs);
    }
    __syncthreads();
    if (tid < 128) atomicAdd(&g_sum[b0 + tid], ssum[tid]);
}

// ---------------- kernel 4: head weight updates (ww + 4 read heads) ----------------
// w_tilde[n] = s0*wg[n+1] + s1*wg[n] + s2*wg[n-1],  wg = g*w_c + (1-g)*w_prev
__global__ __launch_bounds__(256) void heads_kernel(
    const float* __restrict__ wr, const float* __restrict__ ww,
    float* __restrict__ wr_t, float* __restrict__ ww_t)
{
    __shared__ float wc_s[258];
    int b = blockIdx.y;
    int n0 = blockIdx.x * 256;
    int t = threadIdx.x;
    float inv = 1.f / g_sum[b];
    float g = g_gate[b];
    float s0 = g_s[b*Ss+0], s1 = g_s[b*Ss+1], s2 = g_s[b*Ss+2];
    for (int i = t; i < 258; i += 256) {
        int n = (n0 - 1 + i + Nn) & (Nn - 1);
        wc_s[i] = g_t[(size_t)b*Nn + n] * inv;
    }
    __syncthreads();
    int n = n0 + t;
    int nm1 = (n - 1 + Nn) & (Nn - 1);
    int np1 = (n + 1) & (Nn - 1);
    float omg = 1.f - g;
    #pragma unroll
    for (int hd = 0; hd < 5; hd++) {
        const float* prev; float* out;
        if (hd == 0) { prev = ww + (size_t)b*Nn; out = ww_t + (size_t)b*Nn; }
        else {
            size_t off = ((size_t)(hd-1)*Bb + b) * Nn;
            prev = wr + off; out = wr_t + off;
        }
        float pm = __ldg(prev + nm1);
        float pc = __ldg(prev + n);
        float pp = __ldg(prev + np1);
        float wgm = g*wc_s[t]   + omg*pm;
        float wgc = g*wc_s[t+1] + omg*pc;
        float wgp = g*wc_s[t+2] + omg*pp;
        out[n] = s0*wgp + s1*wgc + s2*wgm;
    }
}

// ---------------- kernel 5: mem erase/add GEMM ----------------
// C(N x 128) = ww^T(N,B) @ {e|a}(B,128), K=512. tile 64n x 128c, 128 threads, 8x8.
// grid (256 n-tiles, 2): y=0 -> g_me (uses g_e), y=1 -> g_ma (uses g_a)
__global__ __launch_bounds__(128) void memgemm_kernel(const float* __restrict__ ww)
{
    __shared__ float a_s[16][64];
    __shared__ float ea_s[16][128];
    int tid = threadIdx.x;
    int tx = tid & 15, ty = tid >> 4;          // ty 0..7
    int n0 = blockIdx.x * 64;
    int ct = blockIdx.y;
    const float* base = ct ? g_a : g_e;
    float acc[8][8];
    #pragma unroll
    for (int i = 0; i < 8; i++)
        #pragma unroll
        for (int j = 0; j < 8; j++) acc[i][j] = 0.f;
    int abb = tid >> 3, anl0 = (tid & 7) * 8;
    int ebb = tid >> 3, ec0  = (tid & 7) * 16;
    for (int bc = 0; bc < Bb; bc += 16) {
        *(float4*)(&a_s[abb][anl0])   = *(const float4*)(ww + (size_t)(bc+abb)*Nn + n0 + anl0);
        *(float4*)(&a_s[abb][anl0+4]) = *(const float4*)(ww + (size_t)(bc+abb)*Nn + n0 + anl0 + 4);
        #pragma unroll
        for (int q = 0; q < 4; q++)
            *(float4*)(&ea_s[ebb][ec0 + q*4]) = *(const float4*)(base + (size_t)(bc+ebb)*Mm + ec0 + q*4);
        __syncthreads();
        #pragma unroll
        for (int bb = 0; bb < 16; bb++) {
            float ar[8], br[8];
            *(float4*)(ar)   = *(const float4*)(&a_s[bb][ty*4]);
            *(float4*)(ar+4) = *(const float4*)(&a_s[bb][32 + ty*4]);
            *(float4*)(br)   = *(const float4*)(&ea_s[bb][tx*4]);
            *(float4*)(br+4) = *(const float4*)(&ea_s[bb][64 + tx*4]);
            #pragma unroll
            for (int i = 0; i < 8; i++)
                #pragma unroll
                for (int j = 0; j < 8; j++)
                    acc[i][j] = fmaf(ar[i], br[j], acc[i][j]);
        }
        __syncthreads();
    }
    float* outp = ct ? g_ma : g_me;
    #pragma unroll
    for (int i = 0; i < 8; i++) {
        int rl = (i < 4) ? (ty*4 + i) : (32 + ty*4 + (i-4));
        #pragma unroll
        for (int jj = 0; jj < 2; jj++) {
            int cl = jj ? (64 + tx*4) : (tx*4);
            float4 v; float* vp = (float*)&v;
            #pragma unroll
            for (int q = 0; q < 4; q++) vp[q] = acc[i][jj*4+q];
            *(float4*)(outp + (size_t)(n0+rl)*Mm + cl) = v;
        }
    }
}

// ---------------- kernel 6: m_t epilogue ----------------
__global__ __launch_bounds__(256) void mfinal_kernel(const float* __restrict__ m, float* __restrict__ m_t)
{
    size_t idx = ((size_t)blockIdx.x * 256 + threadIdx.x) * 4;
    float4 mv = *(const float4*)(m + idx);
    float4 ev = *(const float4*)(g_me + idx);
    float4 av = *(const float4*)(g_ma + idx);
    float4 o;
    o.x = mv.x * (1.f - ev.x) + av.x;
    o.y = mv.y * (1.f - ev.y) + av.y;
    o.z = mv.z * (1.f - ev.z) + av.z;
    o.w = mv.w * (1.f - ev.w) + av.w;
    *(float4*)(m_t + idx) = o;
}

// ---------------- kernel 7: r_t GEMM (split-K, atomic accumulate) ----------------
// C(2048 rb x 128) = wr(2048,16384) @ m(16384,128). tile 64x128, 128 threads, 8x8.
// grid (32 row-tiles, 8 k-splits of 2048)
__global__ __launch_bounds__(128) void rt_kernel(
    const float* __restrict__ wr, const float* __restrict__ m, float* __restrict__ r_out)
{
    __shared__ float a_s[16][64];
    __shared__ float b_s[16][128];
    int tid = threadIdx.x;
    int tx = tid & 15, ty = tid >> 4;
    int row0 = blockIdx.x * 64;
    int kb = blockIdx.y * 2048;
    float acc[8][8];
    #pragma unroll
    for (int i = 0; i < 8; i++)
        #pragma unroll
        for (int j = 0; j < 8; j++) acc[i][j] = 0.f;
    int arl = tid >> 1, akk0 = (tid & 1) * 8;
    int bkk = tid >> 3, bc0  = (tid & 7) * 16;
    for (int kc = kb; kc < kb + 2048; kc += 16) {
        float4 va0 = *(const float4*)(wr + (size_t)(row0+arl)*Nn + kc + akk0);
        float4 va1 = *(const float4*)(wr + (size_t)(row0+arl)*Nn + kc + akk0 + 4);
        a_s[akk0+0][arl]=va0.x; a_s[akk0+1][arl]=va0.y; a_s[akk0+2][arl]=va0.z; a_s[akk0+3][arl]=va0.w;
        a_s[akk0+4][arl]=va1.x; a_s[akk0+5][arl]=va1.y; a_s[akk0+6][arl]=va1.z; a_s[akk0+7][arl]=va1.w;
        #pragma unroll
        for (int q = 0; q < 4; q++)
            *(float4*)(&b_s[bkk][bc0 + q*4]) = *(const float4*)(m + (size_t)(kc+bkk)*Mm + bc0 + q*4);
        __syncthreads();
        #pragma unroll
        for (int kk = 0; kk < 16; kk++) {
            float ar[8], br[8];
            *(float4*)(ar)   = *(const float4*)(&a_s[kk][ty*4]);
            *(float4*)(ar+4) = *(const float4*)(&a_s[kk][32 + ty*4]);
            *(float4*)(br)   = *(const float4*)(&b_s[kk][tx*4]);
            *(float4*)(br+4) = *(const float4*)(&b_s[kk][64 + tx*4]);
            #pragma unroll
            for (int i = 0; i < 8; i++)
                #pragma unroll
                for (int j = 0; j < 8; j++)
                    acc[i][j] = fmaf(ar[i], br[j], acc[i][j]);
        }
        __syncthreads();
    }
    #pragma unroll
    for (int i = 0; i < 8; i++) {
        int rl = (i < 4) ? (ty*4 + i) : (32 + ty*4 + (i-4));
        int rb = row0 + rl;
        int r = rb >> 9, b = rb & (Bb - 1);
        float* dst = r_out + ((size_t)b*Rr + r) * Mm;
        #pragma unroll
        for (int j = 0; j < 8; j++) {
            int cl = (j < 4) ? (tx*4 + j) : (64 + tx*4 + (j-4));
            atomicAdd(dst + cl, acc[i][j]);
        }
    }
}

// ---------------- launch ----------------
extern "C" void kernel_launch(void* const* d_in, const int* in_sizes, int n_in,
                              void* d_out, int out_size)
{
    const float* h_t = (const float*)d_in[0];
    const float* wr  = (const float*)d_in[1];
    const float* ww  = (const float*)d_in[2];
    const float* m   = (const float*)d_in[3];
    const float* kw  = (const float*)d_in[4];
    const float* kb  = (const float*)d_in[5];
    const float* bw  = (const float*)d_in[6];
    const float* bbv = (const float*)d_in[7];
    const float* gw  = (const float*)d_in[8];
    const float* gb  = (const float*)d_in[9];
    const float* sw  = (const float*)d_in[10];
    const float* sb  = (const float*)d_in[11];
    // d_in[12], d_in[13]: gamma_w / gamma_b — reference computes but never uses sharpening
    const float* ew  = (const float*)d_in[14];
    const float* eb  = (const float*)d_in[15];
    const float* aw  = (const float*)d_in[16];
    const float* ab  = (const float*)d_in[17];

    float* out  = (float*)d_out;
    float* r_t  = out;                                   // (B,R,M)  262144
    float* wr_t = out + (size_t)Bb*Rr*Mm;                // (R,B,N)  33554432
    float* ww_t = wr_t + (size_t)Rr*Bb*Nn;               // (B,N)    8388608
    float* m_t  = ww_t + (size_t)Bb*Nn;                  // (N,M)    2097152

    ctrl_kernel<<<Bb/8, 256>>>(h_t, kw, kb, bw, bbv, gw, gb, sw, sb, ew, eb, aw, ab);
    prep_kernel<<<2240, 256>>>(m, r_t);
    sim_kernel<<<dim3(Nn/128, Bb/128), 256>>>(m);
    heads_kernel<<<dim3(Nn/256, Bb), 256>>>(wr, ww, wr_t, ww_t);
    memgemm_kernel<<<dim3(Nn/64, 2), 128>>>(ww);
    mfinal_kernel<<<(Nn*Mm)/1024, 256>>>(m, m_t);
    rt_kernel<<<dim3(2048/64, 8), 128>>>(wr, m, r_t);
}

// round 3
// speedup vs baseline: 1.8350x; 1.8350x over previous
#include <cuda_runtime.h>
#include <cuda_bf16.h>

#define Bb 512
#define Hh 1024
#define Nn 16384
#define Mm 128
#define Rr 4
#define Ss 3

#define PADK 40    // row stride (bf16) for 32-wide k tiles (80B, mult of 16)
#define PADW 136   // row stride (bf16) for 128-wide tiles (272B, mult of 16)

// ---------------- scratch (device globals; no allocations allowed) ----------------
__device__ __align__(16) float g_k[Bb*Mm];
__device__ __align__(16) float g_e[Bb*Mm];
__device__ __align__(16) float g_a[Bb*Mm];
__device__ float g_beta[Bb], g_gate[Bb], g_slog[Bb*Ss], g_s[Bb*Ss];
__device__ float g_nk[Bb], g_nm[Nn], g_sum[Bb];
__device__ __align__(16) float g_t[(size_t)Bb*Nn];   // exp(beta*sim), unnormalized
__device__ __align__(16) float g_me[(size_t)Nn*Mm];  // ww^T @ e
__device__ __align__(16) float g_ma[(size_t)Nn*Mm];  // ww^T @ a

// ---------------- HMMA helpers ----------------
__device__ __forceinline__ void ldsm4(unsigned* r, const __nv_bfloat16* p) {
    unsigned a = (unsigned)__cvta_generic_to_shared(p);
    asm volatile("ldmatrix.sync.aligned.m8n8.x4.shared.b16 {%0,%1,%2,%3}, [%4];"
        : "=r"(r[0]), "=r"(r[1]), "=r"(r[2]), "=r"(r[3]) : "r"(a));
}
__device__ __forceinline__ void ldsm4t(unsigned* r, const __nv_bfloat16* p) {
    unsigned a = (unsigned)__cvta_generic_to_shared(p);
    asm volatile("ldmatrix.sync.aligned.m8n8.x4.trans.shared.b16 {%0,%1,%2,%3}, [%4];"
        : "=r"(r[0]), "=r"(r[1]), "=r"(r[2]), "=r"(r[3]) : "r"(a));
}
__device__ __forceinline__ void mma16816(float* c, const unsigned* a, const unsigned* b) {
    asm volatile("mma.sync.aligned.m16n8k16.row.col.f32.bf16.bf16.f32 "
        "{%0,%1,%2,%3}, {%4,%5,%6,%7}, {%8,%9}, {%0,%1,%2,%3};"
        : "+f"(c[0]), "+f"(c[1]), "+f"(c[2]), "+f"(c[3])
        : "r"(a[0]), "r"(a[1]), "r"(a[2]), "r"(a[3]), "r"(b[0]), "r"(b[1]));
}
__device__ __forceinline__ void cvt_store8(__nv_bfloat16* dst, float4 v0, float4 v1) {
    __nv_bfloat162* d = (__nv_bfloat162*)dst;
    d[0] = __float22bfloat162_rn(make_float2(v0.x, v0.y));
    d[1] = __float22bfloat162_rn(make_float2(v0.z, v0.w));
    d[2] = __float22bfloat162_rn(make_float2(v1.x, v1.y));
    d[3] = __float22bfloat162_rn(make_float2(v1.z, v1.w));
}

// ---------------- kernel 1: controller projections ----------------
__global__ __launch_bounds__(256) void ctrl_kernel(
    const float* __restrict__ h,
    const float* __restrict__ kw, const float* __restrict__ kb,
    const float* __restrict__ bw, const float* __restrict__ bbv,
    const float* __restrict__ gw, const float* __restrict__ gb,
    const float* __restrict__ sw, const float* __restrict__ sb,
    const float* __restrict__ ew, const float* __restrict__ eb,
    const float* __restrict__ aw, const float* __restrict__ ab)
{
    __shared__ float h_s[8][Hh];
    int b0 = blockIdx.x * 8;
    for (int i = threadIdx.x; i < 8*Hh; i += 256)
        h_s[i >> 10][i & 1023] = h[(size_t)(b0 + (i >> 10))*Hh + (i & 1023)];
    __syncthreads();
    int warp = threadIdx.x >> 5, lane = threadIdx.x & 31;
    for (int j = warp; j < 3*Mm + 5; j += 8) {
        const float* wrow; float bias; int act;
        if (j < Mm)        { wrow = kw + (size_t)j*Hh;        bias = kb[j];      act = 0; }
        else if (j < 2*Mm) { wrow = ew + (size_t)(j-Mm)*Hh;   bias = eb[j-Mm];   act = 0; }
        else if (j < 3*Mm) { wrow = aw + (size_t)(j-2*Mm)*Hh; bias = ab[j-2*Mm]; act = 0; }
        else if (j == 384) { wrow = bw;                       bias = bbv[0];     act = 2; }
        else if (j == 385) { wrow = gw;                       bias = gb[0];      act = 0; }
        else               { wrow = sw + (size_t)(j-386)*Hh;  bias = sb[j-386];  act = 3; }
        float acc[8];
        #pragma unroll
        for (int q = 0; q < 8; q++) acc[q] = 0.f;
        for (int k = lane; k < Hh; k += 32) {
            float wv = __ldg(wrow + k);
            #pragma unroll
            for (int q = 0; q < 8; q++) acc[q] = fmaf(wv, h_s[q][k], acc[q]);
        }
        #pragma unroll
        for (int q = 0; q < 8; q++) {
            float v = acc[q];
            #pragma unroll
            for (int o = 16; o; o >>= 1) v += __shfl_down_sync(0xffffffffu, v, o);
            if (lane == 0) {
                v += bias;
                if (act == 0) v = fminf(fmaxf(v, 0.f), 1.f);
                else if (act == 2) v = fmaxf(v, 0.f);
                int b = b0 + q;
                if (j < Mm)        g_k[b*Mm + j] = v;
                else if (j < 2*Mm) g_e[b*Mm + (j-Mm)] = v;
                else if (j < 3*Mm) g_a[b*Mm + (j-2*Mm)] = v;
                else if (j == 384) g_beta[b] = v;
                else if (j == 385) g_gate[b] = v;
                else               g_slog[b*Ss + (j-386)] = v;
            }
        }
    }
}

// ---------------- kernel 2: norms, shift softmax, zero init ----------------
__global__ __launch_bounds__(256) void prep_kernel(const float* __restrict__ m, float* __restrict__ r_out)
{
    int warp = threadIdx.x >> 5, lane = threadIdx.x & 31;
    int bidx = blockIdx.x;
    if (bidx < 2048) {
        int n = bidx*8 + warp;
        float4 v = *(const float4*)(m + (size_t)n*Mm + lane*4);
        float ss = v.x*v.x + v.y*v.y + v.z*v.z + v.w*v.w;
        #pragma unroll
        for (int o = 16; o; o >>= 1) ss += __shfl_down_sync(0xffffffffu, ss, o);
        if (lane == 0) g_nm[n] = sqrtf(ss);
    } else if (bidx < 2112) {
        int b = (bidx-2048)*8 + warp;
        float4 v = *(const float4*)(g_k + (size_t)b*Mm + lane*4);
        float ss = v.x*v.x + v.y*v.y + v.z*v.z + v.w*v.w;
        #pragma unroll
        for (int o = 16; o; o >>= 1) ss += __shfl_down_sync(0xffffffffu, ss, o);
        if (lane == 0) {
            g_nk[b] = sqrtf(ss);
            g_sum[b] = 0.f;
            float x0 = g_slog[b*Ss+0], x1 = g_slog[b*Ss+1], x2 = g_slog[b*Ss+2];
            float mx = fmaxf(x0, fmaxf(x1, x2));
            float e0 = expf(x0-mx), e1 = expf(x1-mx), e2 = expf(x2-mx);
            float it = 1.f / (e0+e1+e2);
            g_s[b*Ss+0] = e0*it; g_s[b*Ss+1] = e1*it; g_s[b*Ss+2] = e2*it;
        }
    } else {
        int base = (bidx-2112)*2048 + threadIdx.x*8;
        float4 z = make_float4(0.f,0.f,0.f,0.f);
        *(float4*)(r_out + base)     = z;
        *(float4*)(r_out + base + 4) = z;
    }
}

// ---------------- kernel 3: sim GEMM (HMMA) + exp + row sums ----------------
__global__ __launch_bounds__(256) void sim_hmma(const float* __restrict__ m)
{
    __shared__ __align__(16) __nv_bfloat16 As[128*PADK];
    __shared__ __align__(16) __nv_bfloat16 Bs[128*PADK];
    __shared__ float ssum[128];
    int tid = threadIdx.x, lane = tid & 31, w = tid >> 5;
    int n0 = blockIdx.x * 128, b0 = blockIdx.y * 128;
    int wm = (w >> 1) * 32, wn = (w & 1) * 64;
    float acc[2][8][4];
    #pragma unroll
    for (int i = 0; i < 2; i++)
        #pragma unroll
        for (int j = 0; j < 8; j++)
            #pragma unroll
            for (int q = 0; q < 4; q++) acc[i][j][q] = 0.f;
    if (tid < 128) ssum[tid] = 0.f;
    int rowt = tid >> 1, kbt = (tid & 1) * 16;
    for (int kc = 0; kc < Mm; kc += 32) {
        const float* ap = g_k + (size_t)(b0 + rowt)*Mm + kc + kbt;
        float4 a0 = *(const float4*)(ap), a1 = *(const float4*)(ap+4),
               a2 = *(const float4*)(ap+8), a3 = *(const float4*)(ap+12);
        cvt_store8(&As[rowt*PADK + kbt], a0, a1);
        cvt_store8(&As[rowt*PADK + kbt + 8], a2, a3);
        const float* bp = m + (size_t)(n0 + rowt)*Mm + kc + kbt;
        float4 c0 = *(const float4*)(bp), c1 = *(const float4*)(bp+4),
               c2 = *(const float4*)(bp+8), c3 = *(const float4*)(bp+12);
        cvt_store8(&Bs[rowt*PADK + kbt], c0, c1);
        cvt_store8(&Bs[rowt*PADK + kbt + 8], c2, c3);
        __syncthreads();
        #pragma unroll
        for (int kk = 0; kk < 32; kk += 16) {
            unsigned af[2][4], bf[4][4];
            #pragma unroll
            for (int i = 0; i < 2; i++)
                ldsm4(af[i], &As[(wm + i*16 + (lane & 15))*PADK + kk + (lane >> 4)*8]);
            #pragma unroll
            for (int j = 0; j < 4; j++)
                ldsm4(bf[j], &Bs[(wn + j*16 + (lane & 7) + ((lane >> 4) & 1)*8)*PADK
                                  + kk + ((lane >> 3) & 1)*8]);
            #pragma unroll
            for (int i = 0; i < 2; i++)
                #pragma unroll
                for (int j = 0; j < 4; j++) {
                    mma16816(acc[i][2*j],   af[i], &bf[j][0]);
                    mma16816(acc[i][2*j+1], af[i], &bf[j][2]);
                }
        }
        __syncthreads();
    }
    int r4 = lane >> 2, c2 = (lane & 3)*2;
    #pragma unroll
    for (int i = 0; i < 2; i++) {
        #pragma unroll
        for (int rs = 0; rs < 2; rs++) {
            int bl = wm + i*16 + rs*8 + r4;
            int bg = b0 + bl;
            float be = g_beta[bg], nk = g_nk[bg];
            float rsum = 0.f;
            #pragma unroll
            for (int j8 = 0; j8 < 8; j8++) {
                int ng0 = n0 + wn + j8*8 + c2;
                float s0 = acc[i][j8][rs*2], s1 = acc[i][j8][rs*2+1];
                float v0 = __expf(be * (s0 / (nk * g_nm[ng0]   + 1e-6f)));
                float v1 = __expf(be * (s1 / (nk * g_nm[ng0+1] + 1e-6f)));
                *(float2*)(g_t + (size_t)bg*Nn + ng0) = make_float2(v0, v1);
                rsum += v0 + v1;
            }
            atomicAdd(&ssum[bl], rsum);
        }
    }
    __syncthreads();
    if (tid < 128) atomicAdd(&g_sum[b0 + tid], ssum[tid]);
}

// ---------------- kernel 4: head weight updates (vectorized, aligned) ----------------
__global__ __launch_bounds__(256) void heads2_kernel(
    const float* __restrict__ wr, const float* __restrict__ ww,
    float* __restrict__ wr_t, float* __restrict__ ww_t)
{
    __shared__ __align__(16) float wc_s[1026];
    __shared__ __align__(16) float pv[1032];   // pv[4..1027] = prev[n0..n0+1023]; halo pv[3], pv[1028]
    int b = blockIdx.y, n0 = blockIdx.x * 1024, t = threadIdx.x;
    float inv = 1.f / g_sum[b];
    float g = g_gate[b], omg = 1.f - g;
    float s0 = g_s[b*Ss+0], s1 = g_s[b*Ss+1], s2 = g_s[b*Ss+2];
    const float* gt = g_t + (size_t)b * Nn;
    for (int i = t; i < 1026; i += 256) {
        int n = (n0 - 1 + i + Nn) & (Nn - 1);
        wc_s[i] = gt[n] * inv;
    }
    #pragma unroll
    for (int hd = 0; hd < 5; hd++) {
        const float* prev; float* out;
        if (hd == 0) { prev = ww + (size_t)b*Nn; out = ww_t + (size_t)b*Nn; }
        else {
            size_t off = ((size_t)(hd-1)*Bb + b) * Nn;
            prev = wr + off; out = wr_t + off;
        }
        __syncthreads();
        *(float4*)&pv[4 + 4*t] = *(const float4*)(prev + n0 + 4*t);   // 16B-aligned
        if (t == 0) pv[3] = prev[(n0 - 1 + Nn) & (Nn - 1)];
        if (t == 1) pv[1028] = prev[(n0 + 1024) & (Nn - 1)];
        __syncthreads();
        float w5[6];
        #pragma unroll
        for (int q = 0; q < 6; q++)
            w5[q] = fmaf(g, wc_s[4*t + q], omg * pv[3 + 4*t + q]);
        float4 o;
        o.x = s0*w5[2] + s1*w5[1] + s2*w5[0];
        o.y = s0*w5[3] + s1*w5[2] + s2*w5[1];
        o.z = s0*w5[4] + s1*w5[3] + s2*w5[2];
        o.w = s0*w5[5] + s1*w5[4] + s2*w5[3];
        *(float4*)(out + n0 + 4*t) = o;
    }
}

// ---------------- kernel 5: mem erase/add GEMM (HMMA) ----------------
__global__ __launch_bounds__(256) void memgemm_hmma(const float* __restrict__ ww)
{
    __shared__ __align__(16) __nv_bfloat16 As[32*PADW];
    __shared__ __align__(16) __nv_bfloat16 Bs[32*PADW];
    int tid = threadIdx.x, lane = tid & 31, w = tid >> 5;
    int n0 = blockIdx.x * 128, ct = blockIdx.y;
    const float* eb_ = ct ? g_a : g_e;
    int wm = (w >> 1) * 32, wn = (w & 1) * 64;
    float acc[2][8][4];
    #pragma unroll
    for (int i = 0; i < 2; i++)
        #pragma unroll
        for (int j = 0; j < 8; j++)
            #pragma unroll
            for (int q = 0; q < 4; q++) acc[i][j][q] = 0.f;
    int lrow = tid >> 3, lcb = (tid & 7) * 16;
    for (int bc = 0; bc < Bb; bc += 32) {
        const float* ap = ww + (size_t)(bc + lrow)*Nn + n0 + lcb;
        float4 a0 = *(const float4*)(ap), a1 = *(const float4*)(ap+4),
               a2 = *(const float4*)(ap+8), a3 = *(const float4*)(ap+12);
        cvt_store8(&As[lrow*PADW + lcb], a0, a1);
        cvt_store8(&As[lrow*PADW + lcb + 8], a2, a3);
        const float* bp = eb_ + (size_t)(bc + lrow)*Mm + lcb;
        float4 c0 = *(const float4*)(bp), c1 = *(const float4*)(bp+4),
               c2 = *(const float4*)(bp+8), c3 = *(const float4*)(bp+12);
        cvt_store8(&Bs[lrow*PADW + lcb], c0, c1);
        cvt_store8(&Bs[lrow*PADW + lcb + 8], c2, c3);
        __syncthreads();
        #pragma unroll
        for (int kk = 0; kk < 32; kk += 16) {
            unsigned af[2][4], bf[4][4];
            #pragma unroll
            for (int i = 0; i < 2; i++)
                ldsm4t(af[i], &As[(kk + (lane & 7) + ((lane >> 4) & 1)*8)*PADW
                                   + wm + i*16 + ((lane >> 3) & 1)*8]);
            #pragma unroll
            for (int j = 0; j < 4; j++)
                ldsm4t(bf[j], &Bs[(kk + (lane & 15))*PADW + wn + j*16 + (lane >> 4)*8]);
            #pragma unroll
            for (int i = 0; i < 2; i++)
                #pragma unroll
                for (int j = 0; j < 4; j++) {
                    mma16816(acc[i][2*j],   af[i], &bf[j][0]);
                    mma16816(acc[i][2*j+1], af[i], &bf[j][2]);
                }
        }
        __syncthreads();
    }
    float* outp = ct ? g_ma : g_me;
    int r4 = lane >> 2, c2 = (lane & 3)*2;
    #pragma unroll
    for (int i = 0; i < 2; i++) {
        #pragma unroll
        for (int j8 = 0; j8 < 8; j8++) {
            int row = n0 + wm + i*16 + r4;
            int col = wn + j8*8 + c2;
            *(float2*)(outp + (size_t)row*Mm + col) = make_float2(acc[i][j8][0], acc[i][j8][1]);
            *(float2*)(outp + (size_t)(row+8)*Mm + col) = make_float2(acc[i][j8][2], acc[i][j8][3]);
        }
    }
}

// ---------------- kernel 6: m_t epilogue ----------------
__global__ __launch_bounds__(256) void mfinal_kernel(const float* __restrict__ m, float* __restrict__ m_t)
{
    size_t idx = ((size_t)blockIdx.x * 256 + threadIdx.x) * 4;
    float4 mv = *(const float4*)(m + idx);
    float4 ev = *(const float4*)(g_me + idx);
    float4 av = *(const float4*)(g_ma + idx);
    float4 o;
    o.x = mv.x * (1.f - ev.x) + av.x;
    o.y = mv.y * (1.f - ev.y) + av.y;
    o.z = mv.z * (1.f - ev.z) + av.z;
    o.w = mv.w * (1.f - ev.w) + av.w;
    *(float4*)(m_t + idx) = o;
}

// ---------------- kernel 7: r_t GEMM (HMMA, split-K, atomic accumulate) ----------------
__global__ __launch_bounds__(256) void rt_hmma(
    const float* __restrict__ wr, const float* __restrict__ m, float* __restrict__ r_out)
{
    __shared__ __align__(16) __nv_bfloat16 As[128*PADK];
    __shared__ __align__(16) __nv_bfloat16 Bs[32*PADW];
    int tid = threadIdx.x, lane = tid & 31, w = tid >> 5;
    int row0 = blockIdx.x * 128;
    int kb = blockIdx.y * 2048;
    int wm = (w >> 1) * 32, wn = (w & 1) * 64;
    float acc[2][8][4];
    #pragma unroll
    for (int i = 0; i < 2; i++)
        #pragma unroll
        for (int j = 0; j < 8; j++)
            #pragma unroll
            for (int q = 0; q < 4; q++) acc[i][j][q] = 0.f;
    int arow = tid >> 1, akb = (tid & 1) * 16;
    int brow = tid >> 3, bnb = (tid & 7) * 16;
    const float* aptr = wr + (size_t)(row0 + arow)*Nn + kb + akb;
    const float* bptr = m + (size_t)(kb + brow)*Mm + bnb;
    for (int kc = 0; kc < 2048; kc += 32) {
        float4 a0 = *(const float4*)(aptr), a1 = *(const float4*)(aptr+4),
               a2 = *(const float4*)(aptr+8), a3 = *(const float4*)(aptr+12);
        cvt_store8(&As[arow*PADK + akb], a0, a1);
        cvt_store8(&As[arow*PADK + akb + 8], a2, a3);
        float4 c0 = *(const float4*)(bptr), c1 = *(const float4*)(bptr+4),
               c2 = *(const float4*)(bptr+8), c3 = *(const float4*)(bptr+12);
        cvt_store8(&Bs[brow*PADW + bnb], c0, c1);
        cvt_store8(&Bs[brow*PADW + bnb + 8], c2, c3);
        __syncthreads();
        #pragma unroll
        for (int kk = 0; kk < 32; kk += 16) {
            unsigned af[2][4], bf[4][4];
            #pragma unroll
            for (int i = 0; i < 2; i++)
                ldsm4(af[i], &As[(wm + i*16 + (lane & 15))*PADK + kk + (lane >> 4)*8]);
            #pragma unroll
            for (int j = 0; j < 4; j++)
                ldsm4t(bf[j], &Bs[(kk + (lane & 15))*PADW + wn + j*16 + (lane >> 4)*8]);
            #pragma unroll
            for (int i = 0; i < 2; i++)
                #pragma unroll
                for (int j = 0; j < 4; j++) {
                    mma16816(acc[i][2*j],   af[i], &bf[j][0]);
                    mma16816(acc[i][2*j+1], af[i], &bf[j][2]);
                }
        }
        __syncthreads();
        aptr += 32; bptr += (size_t)32 * Mm;
    }
    int r4 = lane >> 2, c2 = (lane & 3)*2;
    #pragma unroll
    for (int i = 0; i < 2; i++) {
        #pragma unroll
        for (int rs = 0; rs < 2; rs++) {
            int rb = row0 + wm + i*16 + rs*8 + r4;
            int r = rb >> 9, b = rb & (Bb - 1);
            float* dst = r_out + ((size_t)b*Rr + r)*Mm;
            #pragma unroll
            for (int j8 = 0; j8 < 8; j8++) {
                int col = wn + j8*8 + c2;
                atomicAdd(dst + col,     acc[i][j8][rs*2]);
                atomicAdd(dst + col + 1, acc[i][j8][rs*2+1]);
            }
        }
    }
}

// ---------------- launch ----------------
extern "C" void kernel_launch(void* const* d_in, const int* in_sizes, int n_in,
                              void* d_out, int out_size)
{
    const float* h_t = (const float*)d_in[0];
    const float* wr  = (const float*)d_in[1];
    const float* ww  = (const float*)d_in[2];
    const float* m   = (const float*)d_in[3];
    const float* kw  = (const float*)d_in[4];
    const float* kb  = (const float*)d_in[5];
    const float* bw  = (const float*)d_in[6];
    const float* bbv = (const float*)d_in[7];
    const float* gw  = (const float*)d_in[8];
    const float* gb  = (const float*)d_in[9];
    const float* sw  = (const float*)d_in[10];
    const float* sb  = (const float*)d_in[11];
    // d_in[12], d_in[13]: gamma_w / gamma_b — computed but unused by reference output
    const float* ew  = (const float*)d_in[14];
    const float* eb  = (const float*)d_in[15];
    const float* aw  = (const float*)d_in[16];
    const float* ab  = (const float*)d_in[17];

    float* out  = (float*)d_out;
    float* r_t  = out;                                   // (B,R,M)
    float* wr_t = out + (size_t)Bb*Rr*Mm;                // (R,B,N)
    float* ww_t = wr_t + (size_t)Rr*Bb*Nn;               // (B,N)
    float* m_t  = ww_t + (size_t)Bb*Nn;                  // (N,M)

    ctrl_kernel<<<Bb/8, 256>>>(h_t, kw, kb, bw, bbv, gw, gb, sw, sb, ew, eb, aw, ab);
    prep_kernel<<<2240, 256>>>(m, r_t);
    sim_hmma<<<dim3(Nn/128, Bb/128), 256>>>(m);
    heads2_kernel<<<dim3(Nn/1024, Bb), 256>>>(wr, ww, wr_t, ww_t);
    memgemm_hmma<<<dim3(Nn/128, 2), 256>>>(ww);
    mfinal_kernel<<<(Nn*Mm)/1024, 256>>>(m, m_t);
    rt_hmma<<<dim3(2048/128, 8), 256>>>(wr, m, r_t);
}

// round 4
// speedup vs baseline: 2.0394x; 1.1114x over previous
#include <cuda_runtime.h>
#include <cuda_bf16.h>

#define Bb 512
#define Hh 1024
#define Nn 16384
#define Mm 128
#define Rr 4
#define Ss 3

#define PADK 40    // row stride (bf16) for 32-wide k tiles (80B, mult of 16)
#define PADW 136   // row stride (bf16) for 128-wide tiles (272B, mult of 16)

// ---------------- scratch (device globals; no allocations allowed) ----------------
__device__ __align__(16) float g_k[Bb*Mm];
__device__ __align__(16) float g_e[Bb*Mm];
__device__ __align__(16) float g_a[Bb*Mm];
__device__ float g_beta[Bb], g_gate[Bb], g_slog[Bb*Ss], g_s[Bb*Ss];
__device__ float g_nk[Bb], g_nm[Nn], g_sum[Bb];
__device__ __align__(16) float g_t[(size_t)Bb*Nn];   // exp(beta*sim), unnormalized
__device__ __align__(16) float g_me[(size_t)Nn*Mm];  // ww^T @ e
__device__ __align__(16) float g_ma[(size_t)Nn*Mm];  // ww^T @ a

// ---------------- HMMA helpers ----------------
__device__ __forceinline__ void ldsm4(unsigned* r, const __nv_bfloat16* p) {
    unsigned a = (unsigned)__cvta_generic_to_shared(p);
    asm volatile("ldmatrix.sync.aligned.m8n8.x4.shared.b16 {%0,%1,%2,%3}, [%4];"
        : "=r"(r[0]), "=r"(r[1]), "=r"(r[2]), "=r"(r[3]) : "r"(a));
}
__device__ __forceinline__ void ldsm4t(unsigned* r, const __nv_bfloat16* p) {
    unsigned a = (unsigned)__cvta_generic_to_shared(p);
    asm volatile("ldmatrix.sync.aligned.m8n8.x4.trans.shared.b16 {%0,%1,%2,%3}, [%4];"
        : "=r"(r[0]), "=r"(r[1]), "=r"(r[2]), "=r"(r[3]) : "r"(a));
}
__device__ __forceinline__ void mma16816(float* c, const unsigned* a, const unsigned* b) {
    asm volatile("mma.sync.aligned.m16n8k16.row.col.f32.bf16.bf16.f32 "
        "{%0,%1,%2,%3}, {%4,%5,%6,%7}, {%8,%9}, {%0,%1,%2,%3};"
        : "+f"(c[0]), "+f"(c[1]), "+f"(c[2]), "+f"(c[3])
        : "r"(a[0]), "r"(a[1]), "r"(a[2]), "r"(a[3]), "r"(b[0]), "r"(b[1]));
}
__device__ __forceinline__ void cvt_store8(__nv_bfloat16* dst, float4 v0, float4 v1) {
    __nv_bfloat162* d = (__nv_bfloat162*)dst;
    d[0] = __float22bfloat162_rn(make_float2(v0.x, v0.y));
    d[1] = __float22bfloat162_rn(make_float2(v0.z, v0.w));
    d[2] = __float22bfloat162_rn(make_float2(v1.x, v1.y));
    d[3] = __float22bfloat162_rn(make_float2(v1.z, v1.w));
}

// ---------------- kernel 1: controller projections ----------------
__global__ __launch_bounds__(256) void ctrl_kernel(
    const float* __restrict__ h,
    const float* __restrict__ kw, const float* __restrict__ kb,
    const float* __restrict__ bw, const float* __restrict__ bbv,
    const float* __restrict__ gw, const float* __restrict__ gb,
    const float* __restrict__ sw, const float* __restrict__ sb,
    const float* __restrict__ ew, const float* __restrict__ eb,
    const float* __restrict__ aw, const float* __restrict__ ab)
{
    __shared__ float h_s[8][Hh];
    int b0 = blockIdx.x * 8;
    for (int i = threadIdx.x; i < 8*Hh; i += 256)
        h_s[i >> 10][i & 1023] = h[(size_t)(b0 + (i >> 10))*Hh + (i & 1023)];
    __syncthreads();
    int warp = threadIdx.x >> 5, lane = threadIdx.x & 31;
    for (int j = warp; j < 3*Mm + 5; j += 8) {
        const float* wrow; float bias; int act;
        if (j < Mm)        { wrow = kw + (size_t)j*Hh;        bias = kb[j];      act = 0; }
        else if (j < 2*Mm) { wrow = ew + (size_t)(j-Mm)*Hh;   bias = eb[j-Mm];   act = 0; }
        else if (j < 3*Mm) { wrow = aw + (size_t)(j-2*Mm)*Hh; bias = ab[j-2*Mm]; act = 0; }
        else if (j == 384) { wrow = bw;                       bias = bbv[0];     act = 2; }
        else if (j == 385) { wrow = gw;                       bias = gb[0];      act = 0; }
        else               { wrow = sw + (size_t)(j-386)*Hh;  bias = sb[j-386];  act = 3; }
        float acc[8];
        #pragma unroll
        for (int q = 0; q < 8; q++) acc[q] = 0.f;
        for (int k = lane; k < Hh; k += 32) {
            float wv = __ldg(wrow + k);
            #pragma unroll
            for (int q = 0; q < 8; q++) acc[q] = fmaf(wv, h_s[q][k], acc[q]);
        }
        #pragma unroll
        for (int q = 0; q < 8; q++) {
            float v = acc[q];
            #pragma unroll
            for (int o = 16; o; o >>= 1) v += __shfl_down_sync(0xffffffffu, v, o);
            if (lane == 0) {
                v += bias;
                if (act == 0) v = fminf(fmaxf(v, 0.f), 1.f);
                else if (act == 2) v = fmaxf(v, 0.f);
                int b = b0 + q;
                if (j < Mm)        g_k[b*Mm + j] = v;
                else if (j < 2*Mm) g_e[b*Mm + (j-Mm)] = v;
                else if (j < 3*Mm) g_a[b*Mm + (j-2*Mm)] = v;
                else if (j == 384) g_beta[b] = v;
                else if (j == 385) g_gate[b] = v;
                else               g_slog[b*Ss + (j-386)] = v;
            }
        }
    }
}

// ---------------- kernel 2: norms, shift softmax, zero init ----------------
__global__ __launch_bounds__(256) void prep_kernel(const float* __restrict__ m, float* __restrict__ r_out)
{
    int warp = threadIdx.x >> 5, lane = threadIdx.x & 31;
    int bidx = blockIdx.x;
    if (bidx < 2048) {
        int n = bidx*8 + warp;
        float4 v = *(const float4*)(m + (size_t)n*Mm + lane*4);
        float ss = v.x*v.x + v.y*v.y + v.z*v.z + v.w*v.w;
        #pragma unroll
        for (int o = 16; o; o >>= 1) ss += __shfl_down_sync(0xffffffffu, ss, o);
        if (lane == 0) g_nm[n] = sqrtf(ss);
    } else if (bidx < 2112) {
        int b = (bidx-2048)*8 + warp;
        float4 v = *(const float4*)(g_k + (size_t)b*Mm + lane*4);
        float ss = v.x*v.x + v.y*v.y + v.z*v.z + v.w*v.w;
        #pragma unroll
        for (int o = 16; o; o >>= 1) ss += __shfl_down_sync(0xffffffffu, ss, o);
        if (lane == 0) {
            g_nk[b] = sqrtf(ss);
            g_sum[b] = 0.f;
            float x0 = g_slog[b*Ss+0], x1 = g_slog[b*Ss+1], x2 = g_slog[b*Ss+2];
            float mx = fmaxf(x0, fmaxf(x1, x2));
            float e0 = expf(x0-mx), e1 = expf(x1-mx), e2 = expf(x2-mx);
            float it = 1.f / (e0+e1+e2);
            g_s[b*Ss+0] = e0*it; g_s[b*Ss+1] = e1*it; g_s[b*Ss+2] = e2*it;
        }
    } else {
        int base = (bidx-2112)*2048 + threadIdx.x*8;
        float4 z = make_float4(0.f,0.f,0.f,0.f);
        *(float4*)(r_out + base)     = z;
        *(float4*)(r_out + base + 4) = z;
    }
}

// ---------------- kernel 3: sim GEMM (HMMA) + exp + row sums ----------------
__global__ __launch_bounds__(256) void sim_hmma(const float* __restrict__ m)
{
    __shared__ __align__(16) __nv_bfloat16 As[128*PADK];
    __shared__ __align__(16) __nv_bfloat16 Bs[128*PADK];
    __shared__ float ssum[128];
    int tid = threadIdx.x, lane = tid & 31, w = tid >> 5;
    int n0 = blockIdx.x * 128, b0 = blockIdx.y * 128;
    int wm = (w >> 1) * 32, wn = (w & 1) * 64;
    float acc[2][8][4];
    #pragma unroll
    for (int i = 0; i < 2; i++)
        #pragma unroll
        for (int j = 0; j < 8; j++)
            #pragma unroll
            for (int q = 0; q < 4; q++) acc[i][j][q] = 0.f;
    if (tid < 128) ssum[tid] = 0.f;
    int rowt = tid >> 1, kbt = (tid & 1) * 16;
    for (int kc = 0; kc < Mm; kc += 32) {
        const float* ap = g_k + (size_t)(b0 + rowt)*Mm + kc + kbt;
        float4 a0 = *(const float4*)(ap), a1 = *(const float4*)(ap+4),
               a2 = *(const float4*)(ap+8), a3 = *(const float4*)(ap+12);
        cvt_store8(&As[rowt*PADK + kbt], a0, a1);
        cvt_store8(&As[rowt*PADK + kbt + 8], a2, a3);
        const float* bp = m + (size_t)(n0 + rowt)*Mm + kc + kbt;
        float4 c0 = *(const float4*)(bp), c1 = *(const float4*)(bp+4),
               c2 = *(const float4*)(bp+8), c3 = *(const float4*)(bp+12);
        cvt_store8(&Bs[rowt*PADK + kbt], c0, c1);
        cvt_store8(&Bs[rowt*PADK + kbt + 8], c2, c3);
        __syncthreads();
        #pragma unroll
        for (int kk = 0; kk < 32; kk += 16) {
            unsigned af[2][4], bf[4][4];
            #pragma unroll
            for (int i = 0; i < 2; i++)
                ldsm4(af[i], &As[(wm + i*16 + (lane & 15))*PADK + kk + (lane >> 4)*8]);
            #pragma unroll
            for (int j = 0; j < 4; j++)
                ldsm4(bf[j], &Bs[(wn + j*16 + (lane & 7) + ((lane >> 4) & 1)*8)*PADK
                                  + kk + ((lane >> 3) & 1)*8]);
            #pragma unroll
            for (int i = 0; i < 2; i++)
                #pragma unroll
                for (int j = 0; j < 4; j++) {
                    mma16816(acc[i][2*j],   af[i], &bf[j][0]);
                    mma16816(acc[i][2*j+1], af[i], &bf[j][2]);
                }
        }
        __syncthreads();
    }
    int r4 = lane >> 2, c2 = (lane & 3)*2;
    #pragma unroll
    for (int i = 0; i < 2; i++) {
        #pragma unroll
        for (int rs = 0; rs < 2; rs++) {
            int bl = wm + i*16 + rs*8 + r4;
            int bg = b0 + bl;
            float be = g_beta[bg], nk = g_nk[bg];
            float rsum = 0.f;
            #pragma unroll
            for (int j8 = 0; j8 < 8; j8++) {
                int ng0 = n0 + wn + j8*8 + c2;
                float s0 = acc[i][j8][rs*2], s1 = acc[i][j8][rs*2+1];
                float v0 = __expf(be * (s0 / (nk * g_nm[ng0]   + 1e-6f)));
                float v1 = __expf(be * (s1 / (nk * g_nm[ng0+1] + 1e-6f)));
                *(float2*)(g_t + (size_t)bg*Nn + ng0) = make_float2(v0, v1);
                rsum += v0 + v1;
            }
            atomicAdd(&ssum[bl], rsum);
        }
    }
    __syncthreads();
    if (tid < 128) atomicAdd(&g_sum[b0 + tid], ssum[tid]);
}

// ---------------- kernel 4: head weight updates (shuffle stencil, no smem) ----------------
__global__ __launch_bounds__(256) void heads3_kernel(
    const float* __restrict__ wr, const float* __restrict__ ww,
    float* __restrict__ wr_t, float* __restrict__ ww_t)
{
    int b = blockIdx.y;
    int n = blockIdx.x * 1024 + threadIdx.x * 4;
    int lane = threadIdx.x & 31;
    float inv = 1.f / g_sum[b];
    float g = g_gate[b], omg = 1.f - g;
    float s0 = g_s[b*Ss+0], s1 = g_s[b*Ss+1], s2 = g_s[b*Ss+2];
    const float* gt = g_t + (size_t)b * Nn;

    // normalized content weights for this thread's 4 lanes + halos
    float4 wc4 = *(const float4*)(gt + n);
    wc4.x *= inv; wc4.y *= inv; wc4.z *= inv; wc4.w *= inv;
    float wcl = __shfl_up_sync(0xffffffffu, wc4.w, 1);
    float wcr = __shfl_down_sync(0xffffffffu, wc4.x, 1);
    if (lane == 0)  wcl = gt[(n - 1 + Nn) & (Nn - 1)] * inv;
    if (lane == 31) wcr = gt[(n + 4) & (Nn - 1)] * inv;

    #pragma unroll
    for (int hd = 0; hd < 5; hd++) {
        const float* prev; float* out;
        if (hd == 0) { prev = ww + (size_t)b*Nn; out = ww_t + (size_t)b*Nn; }
        else {
            size_t off = ((size_t)(hd-1)*Bb + b) * Nn;
            prev = wr + off; out = wr_t + off;
        }
        float4 p4 = *(const float4*)(prev + n);
        float pl = __shfl_up_sync(0xffffffffu, p4.w, 1);
        float pr = __shfl_down_sync(0xffffffffu, p4.x, 1);
        if (lane == 0)  pl = __ldg(prev + ((n - 1 + Nn) & (Nn - 1)));
        if (lane == 31) pr = __ldg(prev + ((n + 4) & (Nn - 1)));
        float wm1 = fmaf(g, wcl,   omg*pl);
        float w0  = fmaf(g, wc4.x, omg*p4.x);
        float w1  = fmaf(g, wc4.y, omg*p4.y);
        float w2  = fmaf(g, wc4.z, omg*p4.z);
        float w3  = fmaf(g, wc4.w, omg*p4.w);
        float w4  = fmaf(g, wcr,   omg*pr);
        float4 o;
        o.x = s0*w1 + s1*w0 + s2*wm1;
        o.y = s0*w2 + s1*w1 + s2*w0;
        o.z = s0*w3 + s1*w2 + s2*w1;
        o.w = s0*w4 + s1*w3 + s2*w2;
        *(float4*)(out + n) = o;
    }
}

// ---------------- kernel 5: mem erase/add GEMM (HMMA) ----------------
__global__ __launch_bounds__(256) void memgemm_hmma(const float* __restrict__ ww)
{
    __shared__ __align__(16) __nv_bfloat16 As[32*PADW];
    __shared__ __align__(16) __nv_bfloat16 Bs[32*PADW];
    int tid = threadIdx.x, lane = tid & 31, w = tid >> 5;
    int n0 = blockIdx.x * 128, ct = blockIdx.y;
    const float* eb_ = ct ? g_a : g_e;
    int wm = (w >> 1) * 32, wn = (w & 1) * 64;
    float acc[2][8][4];
    #pragma unroll
    for (int i = 0; i < 2; i++)
        #pragma unroll
        for (int j = 0; j < 8; j++)
            #pragma unroll
            for (int q = 0; q < 4; q++) acc[i][j][q] = 0.f;
    int lrow = tid >> 3, lcb = (tid & 7) * 16;
    for (int bc = 0; bc < Bb; bc += 32) {
        const float* ap = ww + (size_t)(bc + lrow)*Nn + n0 + lcb;
        float4 a0 = *(const float4*)(ap), a1 = *(const float4*)(ap+4),
               a2 = *(const float4*)(ap+8), a3 = *(const float4*)(ap+12);
        cvt_store8(&As[lrow*PADW + lcb], a0, a1);
        cvt_store8(&As[lrow*PADW + lcb + 8], a2, a3);
        const float* bp = eb_ + (size_t)(bc + lrow)*Mm + lcb;
        float4 c0 = *(const float4*)(bp), c1 = *(const float4*)(bp+4),
               c2 = *(const float4*)(bp+8), c3 = *(const float4*)(bp+12);
        cvt_store8(&Bs[lrow*PADW + lcb], c0, c1);
        cvt_store8(&Bs[lrow*PADW + lcb + 8], c2, c3);
        __syncthreads();
        #pragma unroll
        for (int kk = 0; kk < 32; kk += 16) {
            unsigned af[2][4], bf[4][4];
            #pragma unroll
            for (int i = 0; i < 2; i++)
                ldsm4t(af[i], &As[(kk + (lane & 7) + ((lane >> 4) & 1)*8)*PADW
                                   + wm + i*16 + ((lane >> 3) & 1)*8]);
            #pragma unroll
            for (int j = 0; j < 4; j++)
                ldsm4t(bf[j], &Bs[(kk + (lane & 15))*PADW + wn + j*16 + (lane >> 4)*8]);
            #pragma unroll
            for (int i = 0; i < 2; i++)
                #pragma unroll
                for (int j = 0; j < 4; j++) {
                    mma16816(acc[i][2*j],   af[i], &bf[j][0]);
                    mma16816(acc[i][2*j+1], af[i], &bf[j][2]);
                }
        }
        __syncthreads();
    }
    float* outp = ct ? g_ma : g_me;
    int r4 = lane >> 2, c2 = (lane & 3)*2;
    #pragma unroll
    for (int i = 0; i < 2; i++) {
        #pragma unroll
        for (int j8 = 0; j8 < 8; j8++) {
            int row = n0 + wm + i*16 + r4;
            int col = wn + j8*8 + c2;
            *(float2*)(outp + (size_t)row*Mm + col) = make_float2(acc[i][j8][0], acc[i][j8][1]);
            *(float2*)(outp + (size_t)(row+8)*Mm + col) = make_float2(acc[i][j8][2], acc[i][j8][3]);
        }
    }
}

// ---------------- kernel 6: m_t epilogue ----------------
__global__ __launch_bounds__(256) void mfinal_kernel(const float* __restrict__ m, float* __restrict__ m_t)
{
    size_t idx = ((size_t)blockIdx.x * 256 + threadIdx.x) * 4;
    float4 mv = *(const float4*)(m + idx);
    float4 ev = *(const float4*)(g_me + idx);
    float4 av = *(const float4*)(g_ma + idx);
    float4 o;
    o.x = mv.x * (1.f - ev.x) + av.x;
    o.y = mv.y * (1.f - ev.y) + av.y;
    o.z = mv.z * (1.f - ev.z) + av.z;
    o.w = mv.w * (1.f - ev.w) + av.w;
    *(float4*)(m_t + idx) = o;
}

// ---------------- kernel 7: r_t GEMM (HMMA, split-K=16, atomic accumulate) ----------------
__global__ __launch_bounds__(256) void rt_hmma(
    const float* __restrict__ wr, const float* __restrict__ m, float* __restrict__ r_out)
{
    __shared__ __align__(16) __nv_bfloat16 As[128*PADK];
    __shared__ __align__(16) __nv_bfloat16 Bs[32*PADW];
    int tid = threadIdx.x, lane = tid & 31, w = tid >> 5;
    int row0 = blockIdx.x * 128;
    int kb = blockIdx.y * 1024;
    int wm = (w >> 1) * 32, wn = (w & 1) * 64;
    float acc[2][8][4];
    #pragma unroll
    for (int i = 0; i < 2; i++)
        #pragma unroll
        for (int j = 0; j < 8; j++)
            #pragma unroll
            for (int q = 0; q < 4; q++) acc[i][j][q] = 0.f;
    int arow = tid >> 1, akb = (tid & 1) * 16;
    int brow = tid >> 3, bnb = (tid & 7) * 16;
    const float* aptr = wr + (size_t)(row0 + arow)*Nn + kb + akb;
    const float* bptr = m + (size_t)(kb + brow)*Mm + bnb;
    for (int kc = 0; kc < 1024; kc += 32) {
        float4 a0 = *(const float4*)(aptr), a1 = *(const float4*)(aptr+4),
               a2 = *(const float4*)(aptr+8), a3 = *(const float4*)(aptr+12);
        cvt_store8(&As[arow*PADK + akb], a0, a1);
        cvt_store8(&As[arow*PADK + akb + 8], a2, a3);
        float4 c0 = *(const float4*)(bptr), c1 = *(const float4*)(bptr+4),
               c2 = *(const float4*)(bptr+8), c3 = *(const float4*)(bptr+12);
        cvt_store8(&Bs[brow*PADW + bnb], c0, c1);
        cvt_store8(&Bs[brow*PADW + bnb + 8], c2, c3);
        __syncthreads();
        #pragma unroll
        for (int kk = 0; kk < 32; kk += 16) {
            unsigned af[2][4], bf[4][4];
            #pragma unroll
            for (int i = 0; i < 2; i++)
                ldsm4(af[i], &As[(wm + i*16 + (lane & 15))*PADK + kk + (lane >> 4)*8]);
            #pragma unroll
            for (int j = 0; j < 4; j++)
                ldsm4t(bf[j], &Bs[(kk + (lane & 15))*PADW + wn + j*16 + (lane >> 4)*8]);
            #pragma unroll
            for (int i = 0; i < 2; i++)
                #pragma unroll
                for (int j = 0; j < 4; j++) {
                    mma16816(acc[i][2*j],   af[i], &bf[j][0]);
                    mma16816(acc[i][2*j+1], af[i], &bf[j][2]);
                }
        }
        __syncthreads();
        aptr += 32; bptr += (size_t)32 * Mm;
    }
    int r4 = lane >> 2, c2 = (lane & 3)*2;
    #pragma unroll
    for (int i = 0; i < 2; i++) {
        #pragma unroll
        for (int rs = 0; rs < 2; rs++) {
            int rb = row0 + wm + i*16 + rs*8 + r4;
            int r = rb >> 9, b = rb & (Bb - 1);
            float* dst = r_out + ((size_t)b*Rr + r)*Mm;
            #pragma unroll
            for (int j8 = 0; j8 < 8; j8++) {
                int col = wn + j8*8 + c2;
                atomicAdd(dst + col,     acc[i][j8][rs*2]);
                atomicAdd(dst + col + 1, acc[i][j8][rs*2+1]);
            }
        }
    }
}

// ---------------- streams/events (host resources, created once at startup) ----------------
namespace {
struct HostRes {
    cudaStream_t s1, s2;
    cudaEvent_t eC, eP, e1, e2;
    HostRes() {
        cudaStreamCreateWithFlags(&s1, cudaStreamNonBlocking);
        cudaStreamCreateWithFlags(&s2, cudaStreamNonBlocking);
        cudaEventCreateWithFlags(&eC, cudaEventDisableTiming);
        cudaEventCreateWithFlags(&eP, cudaEventDisableTiming);
        cudaEventCreateWithFlags(&e1, cudaEventDisableTiming);
        cudaEventCreateWithFlags(&e2, cudaEventDisableTiming);
    }
};
HostRes g_res;
}

// ---------------- launch ----------------
extern "C" void kernel_launch(void* const* d_in, const int* in_sizes, int n_in,
                              void* d_out, int out_size)
{
    const float* h_t = (const float*)d_in[0];
    const float* wr  = (const float*)d_in[1];
    const float* ww  = (const float*)d_in[2];
    const float* m   = (const float*)d_in[3];
    const float* kw  = (const float*)d_in[4];
    const float* kb  = (const float*)d_in[5];
    const float* bw  = (const float*)d_in[6];
    const float* bbv = (const float*)d_in[7];
    const float* gw  = (const float*)d_in[8];
    const float* gb  = (const float*)d_in[9];
    const float* sw  = (const float*)d_in[10];
    const float* sb  = (const float*)d_in[11];
    // d_in[12], d_in[13]: gamma_w / gamma_b — computed but unused by reference output
    const float* ew  = (const float*)d_in[14];
    const float* eb  = (const float*)d_in[15];
    const float* aw  = (const float*)d_in[16];
    const float* ab  = (const float*)d_in[17];

    float* out  = (float*)d_out;
    float* r_t  = out;                                   // (B,R,M)
    float* wr_t = out + (size_t)Bb*Rr*Mm;                // (R,B,N)
    float* ww_t = wr_t + (size_t)Rr*Bb*Nn;               // (B,N)
    float* m_t  = ww_t + (size_t)Bb*Nn;                  // (N,M)

    // legacy stream: critical path
    ctrl_kernel<<<Bb/8, 256>>>(h_t, kw, kb, bw, bbv, gw, gb, sw, sb, ew, eb, aw, ab);
    cudaEventRecord(g_res.eC, 0);
    prep_kernel<<<2240, 256>>>(m, r_t);
    cudaEventRecord(g_res.eP, 0);

    // side stream 2: memgemm -> mfinal (needs ctrl only)
    cudaStreamWaitEvent(g_res.s2, g_res.eC, 0);
    memgemm_hmma<<<dim3(Nn/128, 2), 256, 0, g_res.s2>>>(ww);
    mfinal_kernel<<<(Nn*Mm)/1024, 256, 0, g_res.s2>>>(m, m_t);
    cudaEventRecord(g_res.e2, g_res.s2);

    // side stream 1: r_t GEMM (needs prep's zeroing only)
    cudaStreamWaitEvent(g_res.s1, g_res.eP, 0);
    rt_hmma<<<dim3(2048/128, 16), 256, 0, g_res.s1>>>(wr, m, r_t);
    cudaEventRecord(g_res.e1, g_res.s1);

    // legacy stream continues: sim -> heads
    sim_hmma<<<dim3(Nn/128, Bb/128), 256>>>(m);
    heads3_kernel<<<dim3(Nn/1024, Bb), 256>>>(wr, ww, wr_t, ww_t);

    // join side streams back
    cudaStreamWaitEvent(0, g_res.e1, 0);
    cudaStreamWaitEvent(0, g_res.e2, 0);
}

// round 5
// speedup vs baseline: 2.0644x; 1.0123x over previous
#include <cuda_runtime.h>
#include <cuda_bf16.h>

#define Bb 512
#define Hh 1024
#define Nn 16384
#define Mm 128
#define Rr 4
#define Ss 3

#define PADK 40    // row stride (bf16) for 32-wide k tiles (80B, mult of 16)
#define PADW 136   // row stride (bf16) for 128-wide tiles (272B, mult of 16)
#define PAD64 72   // row stride (bf16) for 64-wide tiles (144B, mult of 16)

// ---------------- scratch (device globals; no allocations allowed) ----------------
__device__ __align__(16) float g_k[Bb*Mm];
__device__ __align__(16) float g_e[Bb*Mm];
__device__ __align__(16) float g_a[Bb*Mm];
__device__ float g_beta[Bb], g_gate[Bb], g_slog[Bb*Ss], g_s[Bb*Ss];
__device__ float g_nk[Bb], g_nm[Nn], g_sum[Bb];   // g_nk/g_nm hold INVERSE norms
__device__ __align__(16) float g_t[(size_t)Bb*Nn]; // exp(beta*sim), unnormalized

// ---------------- HMMA helpers ----------------
__device__ __forceinline__ void ldsm4(unsigned* r, const __nv_bfloat16* p) {
    unsigned a = (unsigned)__cvta_generic_to_shared(p);
    asm volatile("ldmatrix.sync.aligned.m8n8.x4.shared.b16 {%0,%1,%2,%3}, [%4];"
        : "=r"(r[0]), "=r"(r[1]), "=r"(r[2]), "=r"(r[3]) : "r"(a));
}
__device__ __forceinline__ void ldsm4t(unsigned* r, const __nv_bfloat16* p) {
    unsigned a = (unsigned)__cvta_generic_to_shared(p);
    asm volatile("ldmatrix.sync.aligned.m8n8.x4.trans.shared.b16 {%0,%1,%2,%3}, [%4];"
        : "=r"(r[0]), "=r"(r[1]), "=r"(r[2]), "=r"(r[3]) : "r"(a));
}
__device__ __forceinline__ void mma16816(float* c, const unsigned* a, const unsigned* b) {
    asm volatile("mma.sync.aligned.m16n8k16.row.col.f32.bf16.bf16.f32 "
        "{%0,%1,%2,%3}, {%4,%5,%6,%7}, {%8,%9}, {%0,%1,%2,%3};"
        : "+f"(c[0]), "+f"(c[1]), "+f"(c[2]), "+f"(c[3])
        : "r"(a[0]), "r"(a[1]), "r"(a[2]), "r"(a[3]), "r"(b[0]), "r"(b[1]));
}
__device__ __forceinline__ void cvt_store8(__nv_bfloat16* dst, float4 v0, float4 v1) {
    __nv_bfloat162* d = (__nv_bfloat162*)dst;
    d[0] = __float22bfloat162_rn(make_float2(v0.x, v0.y));
    d[1] = __float22bfloat162_rn(make_float2(v0.z, v0.w));
    d[2] = __float22bfloat162_rn(make_float2(v1.x, v1.y));
    d[3] = __float22bfloat162_rn(make_float2(v1.z, v1.w));
}

// ---------------- kernel 1: controller projections ----------------
__global__ __launch_bounds__(256) void ctrl_kernel(
    const float* __restrict__ h,
    const float* __restrict__ kw, const float* __restrict__ kb,
    const float* __restrict__ bw, const float* __restrict__ bbv,
    const float* __restrict__ gw, const float* __restrict__ gb,
    const float* __restrict__ sw, const float* __restrict__ sb,
    const float* __restrict__ ew, const float* __restrict__ eb,
    const float* __restrict__ aw, const float* __restrict__ ab)
{
    __shared__ float h_s[8][Hh];
    int b0 = blockIdx.x * 8;
    for (int i = threadIdx.x; i < 8*Hh; i += 256)
        h_s[i >> 10][i & 1023] = h[(size_t)(b0 + (i >> 10))*Hh + (i & 1023)];
    __syncthreads();
    int warp = threadIdx.x >> 5, lane = threadIdx.x & 31;
    for (int j = warp; j < 3*Mm + 5; j += 8) {
        const float* wrow; float bias; int act;
        if (j < Mm)        { wrow = kw + (size_t)j*Hh;        bias = kb[j];      act = 0; }
        else if (j < 2*Mm) { wrow = ew + (size_t)(j-Mm)*Hh;   bias = eb[j-Mm];   act = 0; }
        else if (j < 3*Mm) { wrow = aw + (size_t)(j-2*Mm)*Hh; bias = ab[j-2*Mm]; act = 0; }
        else if (j == 384) { wrow = bw;                       bias = bbv[0];     act = 2; }
        else if (j == 385) { wrow = gw;                       bias = gb[0];      act = 0; }
        else               { wrow = sw + (size_t)(j-386)*Hh;  bias = sb[j-386];  act = 3; }
        float acc[8];
        #pragma unroll
        for (int q = 0; q < 8; q++) acc[q] = 0.f;
        for (int k = lane; k < Hh; k += 32) {
            float wv = __ldg(wrow + k);
            #pragma unroll
            for (int q = 0; q < 8; q++) acc[q] = fmaf(wv, h_s[q][k], acc[q]);
        }
        #pragma unroll
        for (int q = 0; q < 8; q++) {
            float v = acc[q];
            #pragma unroll
            for (int o = 16; o; o >>= 1) v += __shfl_down_sync(0xffffffffu, v, o);
            if (lane == 0) {
                v += bias;
                if (act == 0) v = fminf(fmaxf(v, 0.f), 1.f);
                else if (act == 2) v = fmaxf(v, 0.f);
                int b = b0 + q;
                if (j < Mm)        g_k[b*Mm + j] = v;
                else if (j < 2*Mm) g_e[b*Mm + (j-Mm)] = v;
                else if (j < 3*Mm) g_a[b*Mm + (j-2*Mm)] = v;
                else if (j == 384) g_beta[b] = v;
                else if (j == 385) g_gate[b] = v;
                else               g_slog[b*Ss + (j-386)] = v;
            }
        }
    }
}

// ---------------- kernel 2: inverse norms, shift softmax, zero init ----------------
__global__ __launch_bounds__(256) void prep_kernel(const float* __restrict__ m, float* __restrict__ r_out)
{
    int warp = threadIdx.x >> 5, lane = threadIdx.x & 31;
    int bidx = blockIdx.x;
    if (bidx < 2048) {
        int n = bidx*8 + warp;
        float4 v = *(const float4*)(m + (size_t)n*Mm + lane*4);
        float ss = v.x*v.x + v.y*v.y + v.z*v.z + v.w*v.w;
        #pragma unroll
        for (int o = 16; o; o >>= 1) ss += __shfl_down_sync(0xffffffffu, ss, o);
        if (lane == 0) g_nm[n] = (ss > 0.f) ? 1.f/sqrtf(ss) : 0.f;
    } else if (bidx < 2112) {
        int b = (bidx-2048)*8 + warp;
        float4 v = *(const float4*)(g_k + (size_t)b*Mm + lane*4);
        float ss = v.x*v.x + v.y*v.y + v.z*v.z + v.w*v.w;
        #pragma unroll
        for (int o = 16; o; o >>= 1) ss += __shfl_down_sync(0xffffffffu, ss, o);
        if (lane == 0) {
            g_nk[b] = (ss > 0.f) ? 1.f/sqrtf(ss) : 0.f;
            g_sum[b] = 0.f;
            float x0 = g_slog[b*Ss+0], x1 = g_slog[b*Ss+1], x2 = g_slog[b*Ss+2];
            float mx = fmaxf(x0, fmaxf(x1, x2));
            float e0 = expf(x0-mx), e1 = expf(x1-mx), e2 = expf(x2-mx);
            float it = 1.f / (e0+e1+e2);
            g_s[b*Ss+0] = e0*it; g_s[b*Ss+1] = e1*it; g_s[b*Ss+2] = e2*it;
        }
    } else {
        int base = (bidx-2112)*2048 + threadIdx.x*8;
        float4 z = make_float4(0.f,0.f,0.f,0.f);
        *(float4*)(r_out + base)     = z;
        *(float4*)(r_out + base + 4) = z;
    }
}

// ---------------- kernel 3: sim GEMM (HMMA, pipelined) + exp2 + row sums ----------------
__global__ __launch_bounds__(256) void sim_hmma(const float* __restrict__ m)
{
    __shared__ __align__(16) __nv_bfloat16 As[128*PADK];
    __shared__ __align__(16) __nv_bfloat16 Bs[128*PADK];
    __shared__ float ssum[128];
    int tid = threadIdx.x, lane = tid & 31, w = tid >> 5;
    int n0 = blockIdx.x * 128, b0 = blockIdx.y * 128;
    int wm = (w >> 1) * 32, wn = (w & 1) * 64;
    float acc[2][8][4];
    #pragma unroll
    for (int i = 0; i < 2; i++)
        #pragma unroll
        for (int j = 0; j < 8; j++)
            #pragma unroll
            for (int q = 0; q < 4; q++) acc[i][j][q] = 0.f;
    if (tid < 128) ssum[tid] = 0.f;
    int rowt = tid >> 1, kbt = (tid & 1) * 16;
    const float* ap = g_k + (size_t)(b0 + rowt)*Mm + kbt;
    const float* bp = m   + (size_t)(n0 + rowt)*Mm + kbt;
    float4 ra0 = *(const float4*)(ap),   ra1 = *(const float4*)(ap+4),
           ra2 = *(const float4*)(ap+8), ra3 = *(const float4*)(ap+12);
    float4 rb0 = *(const float4*)(bp),   rb1 = *(const float4*)(bp+4),
           rb2 = *(const float4*)(bp+8), rb3 = *(const float4*)(bp+12);
    #pragma unroll
    for (int it = 0; it < 4; it++) {
        cvt_store8(&As[rowt*PADK + kbt],     ra0, ra1);
        cvt_store8(&As[rowt*PADK + kbt + 8], ra2, ra3);
        cvt_store8(&Bs[rowt*PADK + kbt],     rb0, rb1);
        cvt_store8(&Bs[rowt*PADK + kbt + 8], rb2, rb3);
        __syncthreads();
        if (it < 3) {                         // prefetch next tile
            ap += 32; bp += 32;
            ra0 = *(const float4*)(ap);   ra1 = *(const float4*)(ap+4);
            ra2 = *(const float4*)(ap+8); ra3 = *(const float4*)(ap+12);
            rb0 = *(const float4*)(bp);   rb1 = *(const float4*)(bp+4);
            rb2 = *(const float4*)(bp+8); rb3 = *(const float4*)(bp+12);
        }
        #pragma unroll
        for (int kk = 0; kk < 32; kk += 16) {
            unsigned af[2][4], bf[4][4];
            #pragma unroll
            for (int i = 0; i < 2; i++)
                ldsm4(af[i], &As[(wm + i*16 + (lane & 15))*PADK + kk + (lane >> 4)*8]);
            #pragma unroll
            for (int j = 0; j < 4; j++)
                ldsm4(bf[j], &Bs[(wn + j*16 + (lane & 7) + ((lane >> 4) & 1)*8)*PADK
                                  + kk + ((lane >> 3) & 1)*8]);
            #pragma unroll
            for (int i = 0; i < 2; i++)
                #pragma unroll
                for (int j = 0; j < 4; j++) {
                    mma16816(acc[i][2*j],   af[i], &bf[j][0]);
                    mma16816(acc[i][2*j+1], af[i], &bf[j][2]);
                }
        }
        __syncthreads();
    }
    int r4 = lane >> 2, c2 = (lane & 3)*2;
    #pragma unroll
    for (int i = 0; i < 2; i++) {
        #pragma unroll
        for (int rs = 0; rs < 2; rs++) {
            int bl = wm + i*16 + rs*8 + r4;
            int bg = b0 + bl;
            float be2 = g_beta[bg] * 1.44269504f * g_nk[bg];   // beta*log2e/|k|
            float rsum = 0.f;
            #pragma unroll
            for (int j8 = 0; j8 < 8; j8++) {
                int ng0 = n0 + wn + j8*8 + c2;
                float v0 = exp2f(be2 * acc[i][j8][rs*2]   * g_nm[ng0]);
                float v1 = exp2f(be2 * acc[i][j8][rs*2+1] * g_nm[ng0+1]);
                *(float2*)(g_t + (size_t)bg*Nn + ng0) = make_float2(v0, v1);
                rsum += v0 + v1;
            }
            atomicAdd(&ssum[bl], rsum);
        }
    }
    __syncthreads();
    if (tid < 128) atomicAdd(&g_sum[b0 + tid], ssum[tid]);
}

// ---------------- kernel 4: head weight updates (hoisted loads, MLP=5) ----------------
__global__ __launch_bounds__(256) void heads4_kernel(
    const float* __restrict__ wr, const float* __restrict__ ww,
    float* __restrict__ wr_t, float* __restrict__ ww_t)
{
    int b = blockIdx.y;
    int n = blockIdx.x * 1024 + threadIdx.x * 4;
    int lane = threadIdx.x & 31;
    float inv = 1.f / g_sum[b];
    float g = g_gate[b], omg = 1.f - g;
    float s0 = g_s[b*Ss+0], s1 = g_s[b*Ss+1], s2 = g_s[b*Ss+2];
    const float* gt = g_t + (size_t)b * Nn;

    const float* prev[5]; float* outp[5];
    prev[0] = ww + (size_t)b*Nn; outp[0] = ww_t + (size_t)b*Nn;
    #pragma unroll
    for (int hd = 1; hd < 5; hd++) {
        size_t off = ((size_t)(hd-1)*Bb + b) * Nn;
        prev[hd] = wr + off; outp[hd] = wr_t + off;
    }

    // issue all 6 main loads up front
    float4 wc4 = *(const float4*)(gt + n);
    float4 p4[5];
    #pragma unroll
    for (int hd = 0; hd < 5; hd++) p4[hd] = *(const float4*)(prev[hd] + n);

    wc4.x *= inv; wc4.y *= inv; wc4.z *= inv; wc4.w *= inv;
    float wcl = __shfl_up_sync(0xffffffffu, wc4.w, 1);
    float wcr = __shfl_down_sync(0xffffffffu, wc4.x, 1);
    float pl[5], pr[5];
    #pragma unroll
    for (int hd = 0; hd < 5; hd++) {
        pl[hd] = __shfl_up_sync(0xffffffffu, p4[hd].w, 1);
        pr[hd] = __shfl_down_sync(0xffffffffu, p4[hd].x, 1);
    }
    if (lane == 0) {
        int nl = (n - 1 + Nn) & (Nn - 1);
        wcl = gt[nl] * inv;
        #pragma unroll
        for (int hd = 0; hd < 5; hd++) pl[hd] = __ldg(prev[hd] + nl);
    }
    if (lane == 31) {
        int nr = (n + 4) & (Nn - 1);
        wcr = gt[nr] * inv;
        #pragma unroll
        for (int hd = 0; hd < 5; hd++) pr[hd] = __ldg(prev[hd] + nr);
    }

    #pragma unroll
    for (int hd = 0; hd < 5; hd++) {
        float wm1 = fmaf(g, wcl,   omg*pl[hd]);
        float w0  = fmaf(g, wc4.x, omg*p4[hd].x);
        float w1  = fmaf(g, wc4.y, omg*p4[hd].y);
        float w2  = fmaf(g, wc4.z, omg*p4[hd].z);
        float w3  = fmaf(g, wc4.w, omg*p4[hd].w);
        float w4  = fmaf(g, wcr,   omg*pr[hd]);
        float4 o;
        o.x = s0*w1 + s1*w0 + s2*wm1;
        o.y = s0*w2 + s1*w1 + s2*w0;
        o.z = s0*w3 + s1*w2 + s2*w1;
        o.w = s0*w4 + s1*w3 + s2*w2;
        *(float4*)(outp[hd] + n) = o;
    }
}

// ---------------- kernel 5: fused erase+add GEMM + m_t epilogue ----------------
// For 64-row n-tile: acc_e = ww^T@e, acc_a = ww^T@a (K=512), m_t = m*(1-acc_e)+acc_a.
__global__ __launch_bounds__(256) void memfused_hmma(
    const float* __restrict__ ww, const float* __restrict__ m, float* __restrict__ m_t)
{
    __shared__ __align__(16) __nv_bfloat16 As[32*PAD64];
    __shared__ __align__(16) __nv_bfloat16 Be[32*PADW];
    __shared__ __align__(16) __nv_bfloat16 Ba[32*PADW];
    int tid = threadIdx.x, lane = tid & 31, w = tid >> 5;
    int n0 = blockIdx.x * 64;
    int wm = (w >> 2) * 32, wn = (w & 3) * 32;
    float ae[2][4][4], aa[2][4][4];
    #pragma unroll
    for (int i = 0; i < 2; i++)
        #pragma unroll
        for (int j = 0; j < 4; j++)
            #pragma unroll
            for (int q = 0; q < 4; q++) { ae[i][j][q] = 0.f; aa[i][j][q] = 0.f; }
    int arw = tid >> 3, acl = (tid & 7) * 8;     // A: 32 rows x 64 cols, 8 floats/thread
    int brw = tid >> 3, bcl = (tid & 7) * 16;    // B: 32 rows x 128 cols, 16 floats/thread
    for (int bc = 0; bc < Bb; bc += 32) {
        const float* apw = ww + (size_t)(bc + arw)*Nn + n0 + acl;
        float4 a0 = *(const float4*)(apw), a1 = *(const float4*)(apw+4);
        cvt_store8(&As[arw*PAD64 + acl], a0, a1);
        const float* ep = g_e + (size_t)(bc + brw)*Mm + bcl;
        float4 e0 = *(const float4*)(ep),   e1 = *(const float4*)(ep+4),
               e2 = *(const float4*)(ep+8), e3 = *(const float4*)(ep+12);
        cvt_store8(&Be[brw*PADW + bcl],     e0, e1);
        cvt_store8(&Be[brw*PADW + bcl + 8], e2, e3);
        const float* apb = g_a + (size_t)(bc + brw)*Mm + bcl;
        float4 f0 = *(const float4*)(apb),   f1 = *(const float4*)(apb+4),
               f2 = *(const float4*)(apb+8), f3 = *(const float4*)(apb+12);
        cvt_store8(&Ba[brw*PADW + bcl],     f0, f1);
        cvt_store8(&Ba[brw*PADW + bcl + 8], f2, f3);
        __syncthreads();
        #pragma unroll
        for (int kk = 0; kk < 32; kk += 16) {
            unsigned af[2][4], bfe[2][4], bfa[2][4];
            #pragma unroll
            for (int i = 0; i < 2; i++)
                ldsm4t(af[i], &As[(kk + (lane & 7) + ((lane >> 4) & 1)*8)*PAD64
                                   + wm + i*16 + ((lane >> 3) & 1)*8]);
            #pragma unroll
            for (int j = 0; j < 2; j++) {
                ldsm4t(bfe[j], &Be[(kk + (lane & 15))*PADW + wn + j*16 + (lane >> 4)*8]);
                ldsm4t(bfa[j], &Ba[(kk + (lane & 15))*PADW + wn + j*16 + (lane >> 4)*8]);
            }
            #pragma unroll
            for (int i = 0; i < 2; i++)
                #pragma unroll
                for (int j = 0; j < 2; j++) {
                    mma16816(ae[i][2*j],   af[i], &bfe[j][0]);
                    mma16816(ae[i][2*j+1], af[i], &bfe[j][2]);
                    mma16816(aa[i][2*j],   af[i], &bfa[j][0]);
                    mma16816(aa[i][2*j+1], af[i], &bfa[j][2]);
                }
        }
        __syncthreads();
    }
    int r4 = lane >> 2, c2 = (lane & 3)*2;
    #pragma unroll
    for (int i = 0; i < 2; i++) {
        #pragma unroll
        for (int j8 = 0; j8 < 4; j8++) {
            int col = wn + j8*8 + c2;
            #pragma unroll
            for (int rs = 0; rs < 2; rs++) {
                int row = n0 + wm + i*16 + rs*8 + r4;
                float me0 = ae[i][j8][rs*2], me1 = ae[i][j8][rs*2+1];
                float ma0 = aa[i][j8][rs*2], ma1 = aa[i][j8][rs*2+1];
                float2 mv = *(const float2*)(m + (size_t)row*Mm + col);
                float2 o;
                o.x = mv.x * (1.f - me0) + ma0;
                o.y = mv.y * (1.f - me1) + ma1;
                *(float2*)(m_t + (size_t)row*Mm + col) = o;
            }
        }
    }
}

// ---------------- kernel 6: r_t GEMM (HMMA, pipelined, split-K=16) ----------------
__global__ __launch_bounds__(256) void rt_hmma(
    const float* __restrict__ wr, const float* __restrict__ m, float* __restrict__ r_out)
{
    __shared__ __align__(16) __nv_bfloat16 As[128*PADK];
    __shared__ __align__(16) __nv_bfloat16 Bs[32*PADW];
    int tid = threadIdx.x, lane = tid & 31, w = tid >> 5;
    int row0 = blockIdx.x * 128;
    int kb = blockIdx.y * 1024;
    int wm = (w >> 1) * 32, wn = (w & 1) * 64;
    float acc[2][8][4];
    #pragma unroll
    for (int i = 0; i < 2; i++)
        #pragma unroll
        for (int j = 0; j < 8; j++)
            #pragma unroll
            for (int q = 0; q < 4; q++) acc[i][j][q] = 0.f;
    int arow = tid >> 1, akb = (tid & 1) * 16;
    int brow = tid >> 3, bnb = (tid & 7) * 16;
    const float* aptr = wr + (size_t)(row0 + arow)*Nn + kb + akb;
    const float* bptr = m + (size_t)(kb + brow)*Mm + bnb;
    float4 ra0 = *(const float4*)(aptr),   ra1 = *(const float4*)(aptr+4),
           ra2 = *(const float4*)(aptr+8), ra3 = *(const float4*)(aptr+12);
    float4 rb0 = *(const float4*)(bptr),   rb1 = *(const float4*)(bptr+4),
           rb2 = *(const float4*)(bptr+8), rb3 = *(const float4*)(bptr+12);
    for (int it = 0; it < 32; it++) {
        cvt_store8(&As[arow*PADK + akb],     ra0, ra1);
        cvt_store8(&As[arow*PADK + akb + 8], ra2, ra3);
        cvt_store8(&Bs[brow*PADW + bnb],     rb0, rb1);
        cvt_store8(&Bs[brow*PADW + bnb + 8], rb2, rb3);
        __syncthreads();
        if (it < 31) {                        // prefetch next tile
            aptr += 32; bptr += (size_t)32 * Mm;
            ra0 = *(const float4*)(aptr);   ra1 = *(const float4*)(aptr+4);
            ra2 = *(const float4*)(aptr+8); ra3 = *(const float4*)(aptr+12);
            rb0 = *(const float4*)(bptr);   rb1 = *(const float4*)(bptr+4);
            rb2 = *(const float4*)(bptr+8); rb3 = *(const float4*)(bptr+12);
        }
        #pragma unroll
        for (int kk = 0; kk < 32; kk += 16) {
            unsigned af[2][4], bf[4][4];
            #pragma unroll
            for (int i = 0; i < 2; i++)
                ldsm4(af[i], &As[(wm + i*16 + (lane & 15))*PADK + kk + (lane >> 4)*8]);
            #pragma unroll
            for (int j = 0; j < 4; j++)
                ldsm4t(bf[j], &Bs[(kk + (lane & 15))*PADW + wn + j*16 + (lane >> 4)*8]);
            #pragma unroll
            for (int i = 0; i < 2; i++)
                #pragma unroll
                for (int j = 0; j < 4; j++) {
                    mma16816(acc[i][2*j],   af[i], &bf[j][0]);
                    mma16816(acc[i][2*j+1], af[i], &bf[j][2]);
                }
        }
        __syncthreads();
    }
    int r4 = lane >> 2, c2 = (lane & 3)*2;
    #pragma unroll
    for (int i = 0; i < 2; i++) {
        #pragma unroll
        for (int rs = 0; rs < 2; rs++) {
            int rb = row0 + wm + i*16 + rs*8 + r4;
            int r = rb >> 9, b = rb & (Bb - 1);
            float* dst = r_out + ((size_t)b*Rr + r)*Mm;
            #pragma unroll
            for (int j8 = 0; j8 < 8; j8++) {
                int col = wn + j8*8 + c2;
                atomicAdd(dst + col,     acc[i][j8][rs*2]);
                atomicAdd(dst + col + 1, acc[i][j8][rs*2+1]);
            }
        }
    }
}

// ---------------- streams/events (host resources, created once at startup) ----------------
namespace {
struct HostRes {
    cudaStream_t s1, s2;
    cudaEvent_t eC, eP, e1, e2;
    HostRes() {
        cudaStreamCreateWithFlags(&s1, cudaStreamNonBlocking);
        cudaStreamCreateWithFlags(&s2, cudaStreamNonBlocking);
        cudaEventCreateWithFlags(&eC, cudaEventDisableTiming);
        cudaEventCreateWithFlags(&eP, cudaEventDisableTiming);
        cudaEventCreateWithFlags(&e1, cudaEventDisableTiming);
        cudaEventCreateWithFlags(&e2, cudaEventDisableTiming);
    }
};
HostRes g_res;
}

// ---------------- launch ----------------
extern "C" void kernel_launch(void* const* d_in, const int* in_sizes, int n_in,
                              void* d_out, int out_size)
{
    const float* h_t = (const float*)d_in[0];
    const float* wr  = (const float*)d_in[1];
    const float* ww  = (const float*)d_in[2];
    const float* m   = (const float*)d_in[3];
    const float* kw  = (const float*)d_in[4];
    const float* kb  = (const float*)d_in[5];
    const float* bw  = (const float*)d_in[6];
    const float* bbv = (const float*)d_in[7];
    const float* gw  = (const float*)d_in[8];
    const float* gb  = (const float*)d_in[9];
    const float* sw  = (const float*)d_in[10];
    const float* sb  = (const float*)d_in[11];
    // d_in[12], d_in[13]: gamma_w / gamma_b — computed but unused by reference output
    const float* ew  = (const float*)d_in[14];
    const float* eb  = (const float*)d_in[15];
    const float* aw  = (const float*)d_in[16];
    const float* ab  = (const float*)d_in[17];

    float* out  = (float*)d_out;
    float* r_t  = out;                                   // (B,R,M)
    float* wr_t = out + (size_t)Bb*Rr*Mm;                // (R,B,N)
    float* ww_t = wr_t + (size_t)Rr*Bb*Nn;               // (B,N)
    float* m_t  = ww_t + (size_t)Bb*Nn;                  // (N,M)

    // legacy stream: critical path
    ctrl_kernel<<<Bb/8, 256>>>(h_t, kw, kb, bw, bbv, gw, gb, sw, sb, ew, eb, aw, ab);
    cudaEventRecord(g_res.eC, 0);
    prep_kernel<<<2240, 256>>>(m, r_t);
    cudaEventRecord(g_res.eP, 0);

    // side stream 2: fused memgemm+epilogue (needs ctrl only)
    cudaStreamWaitEvent(g_res.s2, g_res.eC, 0);
    memfused_hmma<<<Nn/64, 256, 0, g_res.s2>>>(ww, m, m_t);
    cudaEventRecord(g_res.e2, g_res.s2);

    // side stream 1: r_t GEMM (needs prep's zeroing only)
    cudaStreamWaitEvent(g_res.s1, g_res.eP, 0);
    rt_hmma<<<dim3(2048/128, 16), 256, 0, g_res.s1>>>(wr, m, r_t);
    cudaEventRecord(g_res.e1, g_res.s1);

    // legacy stream continues: sim -> heads
    sim_hmma<<<dim3(Nn/128, Bb/128), 256>>>(m);
    heads4_kernel<<<dim3(Nn/1024, Bb), 256>>>(wr, ww, wr_t, ww_t);

    // join side streams back
    cudaStreamWaitEvent(0, g_res.e1, 0);
    cudaStreamWaitEvent(0, g_res.e2, 0);
}

// round 7
// speedup vs baseline: 3.2927x; 1.5950x over previous
#include <cuda_runtime.h>
#include <cuda_bf16.h>

#define Bb 512
#define Hh 1024
#define Nn 16384
#define Mm 128
#define Rr 4
#define Ss 3

#define PADK 40    // row stride (bf16) for 32-wide k tiles (80B, mult of 16)
#define PADW 136   // row stride (bf16) for 128-wide tiles (272B, mult of 16)
#define PAD64 72   // row stride (bf16) for 64-wide tiles (144B, mult of 16)

// ---------------- scratch (device globals; no allocations allowed) ----------------
__device__ __align__(16) float g_k[Bb*Mm];
__device__ __align__(16) float g_e[Bb*Mm];
__device__ __align__(16) float g_a[Bb*Mm];
__device__ float g_beta[Bb], g_gate[Bb], g_slog[Bb*Ss], g_s[Bb*Ss];
__device__ float g_nk[Bb], g_nm[Nn], g_sum[Bb];   // g_nk/g_nm hold INVERSE norms
__device__ __align__(16) float g_t[(size_t)Bb*Nn]; // exp(beta*sim), unnormalized

// ---------------- HMMA helpers ----------------
__device__ __forceinline__ void ldsm4(unsigned* r, const __nv_bfloat16* p) {
    unsigned a = (unsigned)__cvta_generic_to_shared(p);
    asm volatile("ldmatrix.sync.aligned.m8n8.x4.shared.b16 {%0,%1,%2,%3}, [%4];"
        : "=r"(r[0]), "=r"(r[1]), "=r"(r[2]), "=r"(r[3]) : "r"(a));
}
__device__ __forceinline__ void ldsm4t(unsigned* r, const __nv_bfloat16* p) {
    unsigned a = (unsigned)__cvta_generic_to_shared(p);
    asm volatile("ldmatrix.sync.aligned.m8n8.x4.trans.shared.b16 {%0,%1,%2,%3}, [%4];"
        : "=r"(r[0]), "=r"(r[1]), "=r"(r[2]), "=r"(r[3]) : "r"(a));
}
__device__ __forceinline__ void mma16816(float* c, const unsigned* a, const unsigned* b) {
    asm volatile("mma.sync.aligned.m16n8k16.row.col.f32.bf16.bf16.f32 "
        "{%0,%1,%2,%3}, {%4,%5,%6,%7}, {%8,%9}, {%0,%1,%2,%3};"
        : "+f"(c[0]), "+f"(c[1]), "+f"(c[2]), "+f"(c[3])
        : "r"(a[0]), "r"(a[1]), "r"(a[2]), "r"(a[3]), "r"(b[0]), "r"(b[1]));
}
__device__ __forceinline__ void cvt_store8(__nv_bfloat16* dst, float4 v0, float4 v1) {
    __nv_bfloat162* d = (__nv_bfloat162*)dst;
    d[0] = __float22bfloat162_rn(make_float2(v0.x, v0.y));
    d[1] = __float22bfloat162_rn(make_float2(v0.z, v0.w));
    d[2] = __float22bfloat162_rn(make_float2(v1.x, v1.y));
    d[3] = __float22bfloat162_rn(make_float2(v1.z, v1.w));
}

// ---------------- kernel 1: controller projections (4x j-parallel) ----------------
__global__ __launch_bounds__(256) void ctrl_kernel(
    const float* __restrict__ h,
    const float* __restrict__ kw, const float* __restrict__ kb,
    const float* __restrict__ bw, const float* __restrict__ bbv,
    const float* __restrict__ gw, const float* __restrict__ gb,
    const float* __restrict__ sw, const float* __restrict__ sb,
    const float* __restrict__ ew, const float* __restrict__ eb,
    const float* __restrict__ aw, const float* __restrict__ ab)
{
    __shared__ float h_s[8][Hh];
    int b0 = blockIdx.x * 8;
    for (int i = threadIdx.x; i < 8*Hh; i += 256)
        h_s[i >> 10][i & 1023] = h[(size_t)(b0 + (i >> 10))*Hh + (i & 1023)];
    __syncthreads();
    int warp = threadIdx.x >> 5, lane = threadIdx.x & 31;
    for (int j = blockIdx.y*8 + warp; j < 3*Mm + 5; j += 32) {
        const float* wrow; float bias; int act;
        if (j < Mm)        { wrow = kw + (size_t)j*Hh;        bias = kb[j];      act = 0; }
        else if (j < 2*Mm) { wrow = ew + (size_t)(j-Mm)*Hh;   bias = eb[j-Mm];   act = 0; }
        else if (j < 3*Mm) { wrow = aw + (size_t)(j-2*Mm)*Hh; bias = ab[j-2*Mm]; act = 0; }
        else if (j == 384) { wrow = bw;                       bias = bbv[0];     act = 2; }
        else if (j == 385) { wrow = gw;                       bias = gb[0];      act = 0; }
        else               { wrow = sw + (size_t)(j-386)*Hh;  bias = sb[j-386];  act = 3; }
        float acc[8];
        #pragma unroll
        for (int q = 0; q < 8; q++) acc[q] = 0.f;
        for (int k = lane; k < Hh; k += 32) {
            float wv = __ldg(wrow + k);
            #pragma unroll
            for (int q = 0; q < 8; q++) acc[q] = fmaf(wv, h_s[q][k], acc[q]);
        }
        #pragma unroll
        for (int q = 0; q < 8; q++) {
            float v = acc[q];
            #pragma unroll
            for (int o = 16; o; o >>= 1) v += __shfl_down_sync(0xffffffffu, v, o);
            if (lane == 0) {
                v += bias;
                if (act == 0) v = fminf(fmaxf(v, 0.f), 1.f);
                else if (act == 2) v = fmaxf(v, 0.f);
                int b = b0 + q;
                if (j < Mm)        g_k[b*Mm + j] = v;
                else if (j < 2*Mm) g_e[b*Mm + (j-Mm)] = v;
                else if (j < 3*Mm) g_a[b*Mm + (j-2*Mm)] = v;
                else if (j == 384) g_beta[b] = v;
                else if (j == 385) g_gate[b] = v;
                else               g_slog[b*Ss + (j-386)] = v;
            }
        }
    }
}

// ---------------- kernel 2a: m inverse norms + zero r_t (NO ctrl dependency) ----------------
__global__ __launch_bounds__(256) void prep_m_kernel(const float* __restrict__ m, float* __restrict__ r_out)
{
    int warp = threadIdx.x >> 5, lane = threadIdx.x & 31;
    int bidx = blockIdx.x;
    if (bidx < 2048) {
        int n = bidx*8 + warp;
        float4 v = *(const float4*)(m + (size_t)n*Mm + lane*4);
        float ss = v.x*v.x + v.y*v.y + v.z*v.z + v.w*v.w;
        #pragma unroll
        for (int o = 16; o; o >>= 1) ss += __shfl_down_sync(0xffffffffu, ss, o);
        if (lane == 0) g_nm[n] = (ss > 0.f) ? 1.f/sqrtf(ss) : 0.f;
    } else {
        int base = (bidx-2048)*2048 + threadIdx.x*8;
        float4 z = make_float4(0.f,0.f,0.f,0.f);
        *(float4*)(r_out + base)     = z;
        *(float4*)(r_out + base + 4) = z;
    }
}

// ---------------- kernel 2b: k inverse norms + shift softmax (needs ctrl) ----------------
__global__ __launch_bounds__(256) void prep_k_kernel()
{
    int warp = threadIdx.x >> 5, lane = threadIdx.x & 31;
    int b = blockIdx.x*8 + warp;
    float4 v = *(const float4*)(g_k + (size_t)b*Mm + lane*4);
    float ss = v.x*v.x + v.y*v.y + v.z*v.z + v.w*v.w;
    #pragma unroll
    for (int o = 16; o; o >>= 1) ss += __shfl_down_sync(0xffffffffu, ss, o);
    if (lane == 0) {
        g_nk[b] = (ss > 0.f) ? 1.f/sqrtf(ss) : 0.f;
        g_sum[b] = 0.f;
        float x0 = g_slog[b*Ss+0], x1 = g_slog[b*Ss+1], x2 = g_slog[b*Ss+2];
        float mx = fmaxf(x0, fmaxf(x1, x2));
        float e0 = expf(x0-mx), e1 = expf(x1-mx), e2 = expf(x2-mx);
        float it = 1.f / (e0+e1+e2);
        g_s[b*Ss+0] = e0*it; g_s[b*Ss+1] = e1*it; g_s[b*Ss+2] = e2*it;
    }
}

// ---------------- kernel 3: sim GEMM (HMMA, pipelined) + exp2 + row sums ----------------
__global__ __launch_bounds__(256) void sim_hmma(const float* __restrict__ m)
{
    __shared__ __align__(16) __nv_bfloat16 As[128*PADK];
    __shared__ __align__(16) __nv_bfloat16 Bs[128*PADK];
    __shared__ float ssum[128];
    int tid = threadIdx.x, lane = tid & 31, w = tid >> 5;
    int n0 = blockIdx.x * 128, b0 = blockIdx.y * 128;
    int wm = (w >> 1) * 32, wn = (w & 1) * 64;
    float acc[2][8][4];
    #pragma unroll
    for (int i = 0; i < 2; i++)
        #pragma unroll
        for (int j = 0; j < 8; j++)
            #pragma unroll
            for (int q = 0; q < 4; q++) acc[i][j][q] = 0.f;
    if (tid < 128) ssum[tid] = 0.f;
    int rowt = tid >> 1, kbt = (tid & 1) * 16;
    const float* ap = g_k + (size_t)(b0 + rowt)*Mm + kbt;
    const float* bp = m   + (size_t)(n0 + rowt)*Mm + kbt;
    float4 ra0 = *(const float4*)(ap),   ra1 = *(const float4*)(ap+4),
           ra2 = *(const float4*)(ap+8), ra3 = *(const float4*)(ap+12);
    float4 rb0 = *(const float4*)(bp),   rb1 = *(const float4*)(bp+4),
           rb2 = *(const float4*)(bp+8), rb3 = *(const float4*)(bp+12);
    #pragma unroll
    for (int it = 0; it < 4; it++) {
        cvt_store8(&As[rowt*PADK + kbt],     ra0, ra1);
        cvt_store8(&As[rowt*PADK + kbt + 8], ra2, ra3);
        cvt_store8(&Bs[rowt*PADK + kbt],     rb0, rb1);
        cvt_store8(&Bs[rowt*PADK + kbt + 8], rb2, rb3);
        __syncthreads();
        if (it < 3) {
            ap += 32; bp += 32;
            ra0 = *(const float4*)(ap);   ra1 = *(const float4*)(ap+4);
            ra2 = *(const float4*)(ap+8); ra3 = *(const float4*)(ap+12);
            rb0 = *(const float4*)(bp);   rb1 = *(const float4*)(bp+4);
            rb2 = *(const float4*)(bp+8); rb3 = *(const float4*)(bp+12);
        }
        #pragma unroll
        for (int kk = 0; kk < 32; kk += 16) {
            unsigned af[2][4], bf[4][4];
            #pragma unroll
            for (int i = 0; i < 2; i++)
                ldsm4(af[i], &As[(wm + i*16 + (lane & 15))*PADK + kk + (lane >> 4)*8]);
            #pragma unroll
            for (int j = 0; j < 4; j++)
                ldsm4(bf[j], &Bs[(wn + j*16 + (lane & 7) + ((lane >> 4) & 1)*8)*PADK
                                  + kk + ((lane >> 3) & 1)*8]);
            #pragma unroll
            for (int i = 0; i < 2; i++)
                #pragma unroll
                for (int j = 0; j < 4; j++) {
                    mma16816(acc[i][2*j],   af[i], &bf[j][0]);
                    mma16816(acc[i][2*j+1], af[i], &bf[j][2]);
                }
        }
        __syncthreads();
    }
    int r4 = lane >> 2, c2 = (lane & 3)*2;
    #pragma unroll
    for (int i = 0; i < 2; i++) {
        #pragma unroll
        for (int rs = 0; rs < 2; rs++) {
            int bl = wm + i*16 + rs*8 + r4;
            int bg = b0 + bl;
            float be2 = g_beta[bg] * 1.44269504f * g_nk[bg];
            float rsum = 0.f;
            #pragma unroll
            for (int j8 = 0; j8 < 8; j8++) {
                int ng0 = n0 + wn + j8*8 + c2;
                float v0 = exp2f(be2 * acc[i][j8][rs*2]   * g_nm[ng0]);
                float v1 = exp2f(be2 * acc[i][j8][rs*2+1] * g_nm[ng0+1]);
                *(float2*)(g_t + (size_t)bg*Nn + ng0) = make_float2(v0, v1);
                rsum += v0 + v1;
            }
            atomicAdd(&ssum[bl], rsum);
        }
    }
    __syncthreads();
    if (tid < 128) atomicAdd(&g_sum[b0 + tid], ssum[tid]);
}

// ---------------- kernel 4: head weight updates (hoisted loads, MLP=5) ----------------
__global__ __launch_bounds__(256) void heads4_kernel(
    const float* __restrict__ wr, const float* __restrict__ ww,
    float* __restrict__ wr_t, float* __restrict__ ww_t)
{
    int b = blockIdx.y;
    int n = blockIdx.x * 1024 + threadIdx.x * 4;
    int lane = threadIdx.x & 31;
    float inv = 1.f / g_sum[b];
    float g = g_gate[b], omg = 1.f - g;
    float s0 = g_s[b*Ss+0], s1 = g_s[b*Ss+1], s2 = g_s[b*Ss+2];
    const float* gt = g_t + (size_t)b * Nn;

    const float* prev[5]; float* outp[5];
    prev[0] = ww + (size_t)b*Nn; outp[0] = ww_t + (size_t)b*Nn;
    #pragma unroll
    for (int hd = 1; hd < 5; hd++) {
        size_t off = ((size_t)(hd-1)*Bb + b) * Nn;
        prev[hd] = wr + off; outp[hd] = wr_t + off;
    }
    float4 wc4 = *(const float4*)(gt + n);
    float4 p4[5];
    #pragma unroll
    for (int hd = 0; hd < 5; hd++) p4[hd] = *(const float4*)(prev[hd] + n);

    wc4.x *= inv; wc4.y *= inv; wc4.z *= inv; wc4.w *= inv;
    float wcl = __shfl_up_sync(0xffffffffu, wc4.w, 1);
    float wcr = __shfl_down_sync(0xffffffffu, wc4.x, 1);
    float pl[5], pr[5];
    #pragma unroll
    for (int hd = 0; hd < 5; hd++) {
        pl[hd] = __shfl_up_sync(0xffffffffu, p4[hd].w, 1);
        pr[hd] = __shfl_down_sync(0xffffffffu, p4[hd].x, 1);
    }
    if (lane == 0) {
        int nl = (n - 1 + Nn) & (Nn - 1);
        wcl = gt[nl] * inv;
        #pragma unroll
        for (int hd = 0; hd < 5; hd++) pl[hd] = __ldg(prev[hd] + nl);
    }
    if (lane == 31) {
        int nr = (n + 4) & (Nn - 1);
        wcr = gt[nr] * inv;
        #pragma unroll
        for (int hd = 0; hd < 5; hd++) pr[hd] = __ldg(prev[hd] + nr);
    }
    #pragma unroll
    for (int hd = 0; hd < 5; hd++) {
        float wm1 = fmaf(g, wcl,   omg*pl[hd]);
        float w0  = fmaf(g, wc4.x, omg*p4[hd].x);
        float w1  = fmaf(g, wc4.y, omg*p4[hd].y);
        float w2  = fmaf(g, wc4.z, omg*p4[hd].z);
        float w3  = fmaf(g, wc4.w, omg*p4[hd].w);
        float w4  = fmaf(g, wcr,   omg*pr[hd]);
        float4 o;
        o.x = s0*w1 + s1*w0 + s2*wm1;
        o.y = s0*w2 + s1*w1 + s2*w0;
        o.z = s0*w3 + s1*w2 + s2*w1;
        o.w = s0*w4 + s1*w3 + s2*w2;
        *(float4*)(outp[hd] + n) = o;
    }
}

// ---------------- kernel 5: fused erase+add GEMM + m_t epilogue ----------------
__global__ __launch_bounds__(256) void memfused_hmma(
    const float* __restrict__ ww, const float* __restrict__ m, float* __restrict__ m_t)
{
    __shared__ __align__(16) __nv_bfloat16 As[32*PAD64];
    __shared__ __align__(16) __nv_bfloat16 Be[32*PADW];
    __shared__ __align__(16) __nv_bfloat16 Ba[32*PADW];
    int tid = threadIdx.x, lane = tid & 31, w = tid >> 5;
    int n0 = blockIdx.x * 64;
    int wm = (w >> 2) * 32, wn = (w & 3) * 32;
    float ae[2][4][4], aa[2][4][4];
    #pragma unroll
    for (int i = 0; i < 2; i++)
        #pragma unroll
        for (int j = 0; j < 4; j++)
            #pragma unroll
            for (int q = 0; q < 4; q++) { ae[i][j][q] = 0.f; aa[i][j][q] = 0.f; }
    int arw = tid >> 3, acl = (tid & 7) * 8;
    int brw = tid >> 3, bcl = (tid & 7) * 16;
    for (int bc = 0; bc < Bb; bc += 32) {
        const float* apw = ww + (size_t)(bc + arw)*Nn + n0 + acl;
        float4 a0 = *(const float4*)(apw), a1 = *(const float4*)(apw+4);
        cvt_store8(&As[arw*PAD64 + acl], a0, a1);
        const float* ep = g_e + (size_t)(bc + brw)*Mm + bcl;
        float4 e0 = *(const float4*)(ep),   e1 = *(const float4*)(ep+4),
               e2 = *(const float4*)(ep+8), e3 = *(const float4*)(ep+12);
        cvt_store8(&Be[brw*PADW + bcl],     e0, e1);
        cvt_store8(&Be[brw*PADW + bcl + 8], e2, e3);
        const float* apb = g_a + (size_t)(bc + brw)*Mm + bcl;
        float4 f0 = *(const float4*)(apb),   f1 = *(const float4*)(apb+4),
               f2 = *(const float4*)(apb+8), f3 = *(const float4*)(apb+12);
        cvt_store8(&Ba[brw*PADW + bcl],     f0, f1);
        cvt_store8(&Ba[brw*PADW + bcl + 8], f2, f3);
        __syncthreads();
        #pragma unroll
        for (int kk = 0; kk < 32; kk += 16) {
            unsigned af[2][4], bfe[2][4], bfa[2][4];
            #pragma unroll
            for (int i = 0; i < 2; i++)
                ldsm4t(af[i], &As[(kk + (lane & 7) + ((lane >> 4) & 1)*8)*PAD64
                                   + wm + i*16 + ((lane >> 3) & 1)*8]);
            #pragma unroll
            for (int j = 0; j < 2; j++) {
                ldsm4t(bfe[j], &Be[(kk + (lane & 15))*PADW + wn + j*16 + (lane >> 4)*8]);
                ldsm4t(bfa[j], &Ba[(kk + (lane & 15))*PADW + wn + j*16 + (lane >> 4)*8]);
            }
            #pragma unroll
            for (int i = 0; i < 2; i++)
                #pragma unroll
                for (int j = 0; j < 2; j++) {
                    mma16816(ae[i][2*j],   af[i], &bfe[j][0]);
                    mma16816(ae[i][2*j+1], af[i], &bfe[j][2]);
                    mma16816(aa[i][2*j],   af[i], &bfa[j][0]);
                    mma16816(aa[i][2*j+1], af[i], &bfa[j][2]);
                }
        }
        __syncthreads();
    }
    int r4 = lane >> 2, c2 = (lane & 3)*2;
    #pragma unroll
    for (int i = 0; i < 2; i++) {
        #pragma unroll
        for (int j8 = 0; j8 < 4; j8++) {
            int col = wn + j8*8 + c2;
            #pragma unroll
            for (int rs = 0; rs < 2; rs++) {
                int row = n0 + wm + i*16 + rs*8 + r4;
                float me0 = ae[i][j8][rs*2], me1 = ae[i][j8][rs*2+1];
                float ma0 = aa[i][j8][rs*2], ma1 = aa[i][j8][rs*2+1];
                float2 mv = *(const float2*)(m + (size_t)row*Mm + col);
                float2 o;
                o.x = mv.x * (1.f - me0) + ma0;
                o.y = mv.y * (1.f - me1) + ma1;
                *(float2*)(m_t + (size_t)row*Mm + col) = o;
            }
        }
    }
}

// ---------------- kernel 6: r_t GEMM v3 (64x128 tile, split-K=32, 1-barrier DB) ----------------
__global__ __launch_bounds__(256, 2) void rt_hmma3(
    const float* __restrict__ wr, const float* __restrict__ m, float* __restrict__ r_out)
{
    __shared__ __align__(16) __nv_bfloat16 As[2][64*PADK];
    __shared__ __align__(16) __nv_bfloat16 Bs[2][32*PADW];
    int tid = threadIdx.x, lane = tid & 31, w = tid >> 5;
    int row0 = blockIdx.x * 64;
    int kb = blockIdx.y * 512;
    int wm = (w >> 2) * 32, wn = (w & 3) * 32;
    float acc[2][4][4];
    #pragma unroll
    for (int i = 0; i < 2; i++)
        #pragma unroll
        for (int j = 0; j < 4; j++)
            #pragma unroll
            for (int q = 0; q < 4; q++) acc[i][j][q] = 0.f;
    int arow = tid >> 2, akb = (tid & 3) * 8;     // A: 64 rows x 32 k, 8 floats/thr
    int brow = tid >> 3, bnb = (tid & 7) * 16;    // B: 32 k x 128 n, 16 floats/thr
    const float* aptr = wr + (size_t)(row0 + arow)*Nn + kb + akb;
    const float* bptr = m + (size_t)(kb + brow)*Mm + bnb;
    float4 ra0 = *(const float4*)(aptr), ra1 = *(const float4*)(aptr+4);
    float4 rb0 = *(const float4*)(bptr),   rb1 = *(const float4*)(bptr+4),
           rb2 = *(const float4*)(bptr+8), rb3 = *(const float4*)(bptr+12);
    for (int it = 0; it < 16; it++) {
        __nv_bfloat16* Ab = As[it & 1];
        __nv_bfloat16* Bbf = Bs[it & 1];
        cvt_store8(&Ab[arow*PADK + akb], ra0, ra1);
        cvt_store8(&Bbf[brow*PADW + bnb],     rb0, rb1);
        cvt_store8(&Bbf[brow*PADW + bnb + 8], rb2, rb3);
        if (it < 15) {                    // issue next LDGs immediately
            aptr += 32; bptr += (size_t)32 * Mm;
            ra0 = *(const float4*)(aptr); ra1 = *(const float4*)(aptr+4);
            rb0 = *(const float4*)(bptr);   rb1 = *(const float4*)(bptr+4);
            rb2 = *(const float4*)(bptr+8); rb3 = *(const float4*)(bptr+12);
        }
        __syncthreads();                  // single barrier per iteration
        #pragma unroll
        for (int kk = 0; kk < 32; kk += 16) {
            unsigned af[2][4], bf[2][4];
            #pragma unroll
            for (int i = 0; i < 2; i++)
                ldsm4(af[i], &Ab[(wm + i*16 + (lane & 15))*PADK + kk + (lane >> 4)*8]);
            #pragma unroll
            for (int j = 0; j < 2; j++)
                ldsm4t(bf[j], &Bbf[(kk + (lane & 15))*PADW + wn + j*16 + (lane >> 4)*8]);
            #pragma unroll
            for (int i = 0; i < 2; i++)
                #pragma unroll
                for (int j = 0; j < 2; j++) {
                    mma16816(acc[i][2*j],   af[i], &bf[j][0]);
                    mma16816(acc[i][2*j+1], af[i], &bf[j][2]);
                }
        }
    }
    int r4 = lane >> 2, c2 = (lane & 3)*2;
    #pragma unroll
    for (int i = 0; i < 2; i++) {
        #pragma unroll
        for (int rs = 0; rs < 2; rs++) {
            int rb = row0 + wm + i*16 + rs*8 + r4;
            int r = rb >> 9, b = rb & (Bb - 1);
            float* dst = r_out + ((size_t)b*Rr + r)*Mm;
            #pragma unroll
            for (int j8 = 0; j8 < 4; j8++) {
                int col = wn + j8*8 + c2;
                atomicAdd(dst + col,     acc[i][j8][rs*2]);
                atomicAdd(dst + col + 1, acc[i][j8][rs*2+1]);
            }
        }
    }
}

// ---------------- streams/events (host resources, created once at startup) ----------------
namespace {
struct HostRes {
    cudaStream_t s1, s2;
    cudaEvent_t e0, eC, eM, e1, e2;
    HostRes() {
        cudaStreamCreateWithFlags(&s1, cudaStreamNonBlocking);
        cudaStreamCreateWithFlags(&s2, cudaStreamNonBlocking);
        cudaEventCreateWithFlags(&e0, cudaEventDisableTiming);
        cudaEventCreateWithFlags(&eC, cudaEventDisableTiming);
        cudaEventCreateWithFlags(&eM, cudaEventDisableTiming);
        cudaEventCreateWithFlags(&e1, cudaEventDisableTiming);
        cudaEventCreateWithFlags(&e2, cudaEventDisableTiming);
    }
};
HostRes g_res;
}

// ---------------- launch ----------------
extern "C" void kernel_launch(void* const* d_in, const int* in_sizes, int n_in,
                              void* d_out, int out_size)
{
    const float* h_t = (const float*)d_in[0];
    const float* wr  = (const float*)d_in[1];
    const float* ww  = (const float*)d_in[2];
    const float* m   = (const float*)d_in[3];
    const float* kw  = (const float*)d_in[4];
    const float* kb  = (const float*)d_in[5];
    const float* bw  = (const float*)d_in[6];
    const float* bbv = (const float*)d_in[7];
    const float* gw  = (const float*)d_in[8];
    const float* gb  = (const float*)d_in[9];
    const float* sw  = (const float*)d_in[10];
    const float* sb  = (const float*)d_in[11];
    // d_in[12], d_in[13]: gamma_w / gamma_b — computed but unused by reference output
    const float* ew  = (const float*)d_in[14];
    const float* eb  = (const float*)d_in[15];
    const float* aw  = (const float*)d_in[16];
    const float* ab  = (const float*)d_in[17];

    float* out  = (float*)d_out;
    float* r_t  = out;                                   // (B,R,M)
    float* wr_t = out + (size_t)Bb*Rr*Mm;                // (R,B,N)
    float* ww_t = wr_t + (size_t)Rr*Bb*Nn;               // (B,N)
    float* m_t  = ww_t + (size_t)Bb*Nn;                  // (N,M)

    // Root event on the capture (legacy) stream — REQUIRED so side streams
    // are pulled into the capture before any work is launched on them.
    cudaEventRecord(g_res.e0, 0);

    // side stream 1: prep_m -> rt GEMM (independent of ctrl; overlaps everything)
    cudaStreamWaitEvent(g_res.s1, g_res.e0, 0);
    prep_m_kernel<<<2176, 256, 0, g_res.s1>>>(m, r_t);
    cudaEventRecord(g_res.eM, g_res.s1);
    rt_hmma3<<<dim3(2048/64, 32), 256, 0, g_res.s1>>>(wr, m, r_t);
    cudaEventRecord(g_res.e1, g_res.s1);

    // legacy stream: critical path
    ctrl_kernel<<<dim3(Bb/8, 4), 256>>>(h_t, kw, kb, bw, bbv, gw, gb, sw, sb, ew, eb, aw, ab);
    cudaEventRecord(g_res.eC, 0);
    prep_k_kernel<<<Bb/8, 256>>>();

    // side stream 2: fused memgemm+epilogue (needs ctrl only)
    cudaStreamWaitEvent(g_res.s2, g_res.eC, 0);
    memfused_hmma<<<Nn/64, 256, 0, g_res.s2>>>(ww, m, m_t);
    cudaEventRecord(g_res.e2, g_res.s2);

    // legacy stream continues: sim (needs prep_k + m-norms) -> heads
    cudaStreamWaitEvent(0, g_res.eM, 0);
    sim_hmma<<<dim3(Nn/128, Bb/128), 256>>>(m);
    heads4_kernel<<<dim3(Nn/1024, Bb), 256>>>(wr, ww, wr_t, ww_t);

    // join side streams back
    cudaStreamWaitEvent(0, g_res.e1, 0);
    cudaStreamWaitEvent(0, g_res.e2, 0);
}

// round 8
// speedup vs baseline: 3.5587x; 1.0808x over previous
#include <cuda_runtime.h>
#include <cuda_bf16.h>

#define Bb 512
#define Hh 1024
#define Nn 16384
#define Mm 128
#define Rr 4
#define Ss 3

#define PADK 40
#define PADW 136
#define PAD64 72

// ---------------- scratch ----------------
__device__ __align__(16) float g_k[Bb*Mm];
__device__ __align__(16) float g_e[Bb*Mm];
__device__ __align__(16) float g_a[Bb*Mm];
__device__ float g_beta[Bb], g_gate[Bb], g_slog[Bb*Ss], g_s[Bb*Ss];
__device__ float g_nk[Bb], g_nm[Nn], g_sum[Bb];   // INVERSE norms
__device__ __align__(16) float g_t[(size_t)Bb*Nn];

// ---------------- helpers ----------------
__device__ __forceinline__ void ldsm4(unsigned* r, const __nv_bfloat16* p) {
    unsigned a = (unsigned)__cvta_generic_to_shared(p);
    asm volatile("ldmatrix.sync.aligned.m8n8.x4.shared.b16 {%0,%1,%2,%3}, [%4];"
        : "=r"(r[0]), "=r"(r[1]), "=r"(r[2]), "=r"(r[3]) : "r"(a));
}
__device__ __forceinline__ void ldsm4t(unsigned* r, const __nv_bfloat16* p) {
    unsigned a = (unsigned)__cvta_generic_to_shared(p);
    asm volatile("ldmatrix.sync.aligned.m8n8.x4.trans.shared.b16 {%0,%1,%2,%3}, [%4];"
        : "=r"(r[0]), "=r"(r[1]), "=r"(r[2]), "=r"(r[3]) : "r"(a));
}
__device__ __forceinline__ void mma16816(float* c, const unsigned* a, const unsigned* b) {
    asm volatile("mma.sync.aligned.m16n8k16.row.col.f32.bf16.bf16.f32 "
        "{%0,%1,%2,%3}, {%4,%5,%6,%7}, {%8,%9}, {%0,%1,%2,%3};"
        : "+f"(c[0]), "+f"(c[1]), "+f"(c[2]), "+f"(c[3])
        : "r"(a[0]), "r"(a[1]), "r"(a[2]), "r"(a[3]), "r"(b[0]), "r"(b[1]));
}
__device__ __forceinline__ void cvt_store8(__nv_bfloat16* dst, float4 v0, float4 v1) {
    __nv_bfloat162* d = (__nv_bfloat162*)dst;
    d[0] = __float22bfloat162_rn(make_float2(v0.x, v0.y));
    d[1] = __float22bfloat162_rn(make_float2(v0.z, v0.w));
    d[2] = __float22bfloat162_rn(make_float2(v1.x, v1.y));
    d[3] = __float22bfloat162_rn(make_float2(v1.z, v1.w));
}

// exp2 on the FMA pipe — no MUFU. Valid for |x| < ~60 (our args are |x|<~10).
__device__ __forceinline__ float fast_exp2(float x) {
    float t = x + 12582912.0f;                       // 2^23 + 2^22: rounds to int
    int ri = __float_as_int(t) - 0x4B400000;         // integer part from mantissa bits
    float f = x - (t - 12582912.0f);                 // f in [-0.5, 0.5]
    float p = 0.0013333558f;                         // Taylor of 2^f = e^{f ln2}
    p = fmaf(p, f, 0.0096181298f);
    p = fmaf(p, f, 0.0555041087f);
    p = fmaf(p, f, 0.2402265070f);
    p = fmaf(p, f, 0.6931471806f);
    p = fmaf(p, f, 1.0f);
    return __int_as_float(__float_as_int(p) + (ri << 23));
}

// ---------------- kernel 1: controller projections (8x j-parallel) ----------------
__global__ __launch_bounds__(256) void ctrl_kernel(
    const float* __restrict__ h,
    const float* __restrict__ kw, const float* __restrict__ kb,
    const float* __restrict__ bw, const float* __restrict__ bbv,
    const float* __restrict__ gw, const float* __restrict__ gb,
    const float* __restrict__ sw, const float* __restrict__ sb,
    const float* __restrict__ ew, const float* __restrict__ eb,
    const float* __restrict__ aw, const float* __restrict__ ab)
{
    __shared__ float h_s[8][Hh];
    int b0 = blockIdx.x * 8;
    for (int i = threadIdx.x; i < 8*Hh; i += 256)
        h_s[i >> 10][i & 1023] = h[(size_t)(b0 + (i >> 10))*Hh + (i & 1023)];
    __syncthreads();
    int warp = threadIdx.x >> 5, lane = threadIdx.x & 31;
    for (int j = blockIdx.y*8 + warp; j < 3*Mm + 5; j += 64) {
        const float* wrow; float bias; int act;
        if (j < Mm)        { wrow = kw + (size_t)j*Hh;        bias = kb[j];      act = 0; }
        else if (j < 2*Mm) { wrow = ew + (size_t)(j-Mm)*Hh;   bias = eb[j-Mm];   act = 0; }
        else if (j < 3*Mm) { wrow = aw + (size_t)(j-2*Mm)*Hh; bias = ab[j-2*Mm]; act = 0; }
        else if (j == 384) { wrow = bw;                       bias = bbv[0];     act = 2; }
        else if (j == 385) { wrow = gw;                       bias = gb[0];      act = 0; }
        else               { wrow = sw + (size_t)(j-386)*Hh;  bias = sb[j-386];  act = 3; }
        float acc[8];
        #pragma unroll
        for (int q = 0; q < 8; q++) acc[q] = 0.f;
        for (int k = lane; k < Hh; k += 32) {
            float wv = __ldg(wrow + k);
            #pragma unroll
            for (int q = 0; q < 8; q++) acc[q] = fmaf(wv, h_s[q][k], acc[q]);
        }
        #pragma unroll
        for (int q = 0; q < 8; q++) {
            float v = acc[q];
            #pragma unroll
            for (int o = 16; o; o >>= 1) v += __shfl_down_sync(0xffffffffu, v, o);
            if (lane == 0) {
                v += bias;
                if (act == 0) v = fminf(fmaxf(v, 0.f), 1.f);
                else if (act == 2) v = fmaxf(v, 0.f);
                int b = b0 + q;
                if (j < Mm)        g_k[b*Mm + j] = v;
                else if (j < 2*Mm) g_e[b*Mm + (j-Mm)] = v;
                else if (j < 3*Mm) g_a[b*Mm + (j-2*Mm)] = v;
                else if (j == 384) g_beta[b] = v;
                else if (j == 385) g_gate[b] = v;
                else               g_slog[b*Ss + (j-386)] = v;
            }
        }
    }
}

// ---------------- kernel 2a: m inverse norms + zero r_t ----------------
__global__ __launch_bounds__(256) void prep_m_kernel(const float* __restrict__ m, float* __restrict__ r_out)
{
    int warp = threadIdx.x >> 5, lane = threadIdx.x & 31;
    int bidx = blockIdx.x;
    if (bidx < 2048) {
        int n = bidx*8 + warp;
        float4 v = *(const float4*)(m + (size_t)n*Mm + lane*4);
        float ss = v.x*v.x + v.y*v.y + v.z*v.z + v.w*v.w;
        #pragma unroll
        for (int o = 16; o; o >>= 1) ss += __shfl_down_sync(0xffffffffu, ss, o);
        if (lane == 0) g_nm[n] = (ss > 0.f) ? 1.f/sqrtf(ss) : 0.f;
    } else {
        int base = (bidx-2048)*2048 + threadIdx.x*8;
        float4 z = make_float4(0.f,0.f,0.f,0.f);
        *(float4*)(r_out + base)     = z;
        *(float4*)(r_out + base + 4) = z;
    }
}

// ---------------- kernel 2b: k inverse norms + shift softmax ----------------
__global__ __launch_bounds__(256) void prep_k_kernel()
{
    int warp = threadIdx.x >> 5, lane = threadIdx.x & 31;
    int b = blockIdx.x*8 + warp;
    float4 v = *(const float4*)(g_k + (size_t)b*Mm + lane*4);
    float ss = v.x*v.x + v.y*v.y + v.z*v.z + v.w*v.w;
    #pragma unroll
    for (int o = 16; o; o >>= 1) ss += __shfl_down_sync(0xffffffffu, ss, o);
    if (lane == 0) {
        g_nk[b] = (ss > 0.f) ? 1.f/sqrtf(ss) : 0.f;
        g_sum[b] = 0.f;
        float x0 = g_slog[b*Ss+0], x1 = g_slog[b*Ss+1], x2 = g_slog[b*Ss+2];
        float mx = fmaxf(x0, fmaxf(x1, x2));
        float e0 = expf(x0-mx), e1 = expf(x1-mx), e2 = expf(x2-mx);
        float it = 1.f / (e0+e1+e2);
        g_s[b*Ss+0] = e0*it; g_s[b*Ss+1] = e1*it; g_s[b*Ss+2] = e2*it;
    }
}

// ---------------- kernel 3: sim GEMM + poly-exp2 + row sums ----------------
__global__ __launch_bounds__(256) void sim_hmma(const float* __restrict__ m)
{
    __shared__ __align__(16) __nv_bfloat16 As[128*PADK];
    __shared__ __align__(16) __nv_bfloat16 Bs[128*PADK];
    __shared__ float ssum[128];
    int tid = threadIdx.x, lane = tid & 31, w = tid >> 5;
    int n0 = blockIdx.x * 128, b0 = blockIdx.y * 128;
    int wm = (w >> 1) * 32, wn = (w & 1) * 64;
    float acc[2][8][4];
    #pragma unroll
    for (int i = 0; i < 2; i++)
        #pragma unroll
        for (int j = 0; j < 8; j++)
            #pragma unroll
            for (int q = 0; q < 4; q++) acc[i][j][q] = 0.f;
    if (tid < 128) ssum[tid] = 0.f;
    int rowt = tid >> 1, kbt = (tid & 1) * 16;
    const float* ap = g_k + (size_t)(b0 + rowt)*Mm + kbt;
    const float* bp = m   + (size_t)(n0 + rowt)*Mm + kbt;
    float4 ra0 = *(const float4*)(ap),   ra1 = *(const float4*)(ap+4),
           ra2 = *(const float4*)(ap+8), ra3 = *(const float4*)(ap+12);
    float4 rb0 = *(const float4*)(bp),   rb1 = *(const float4*)(bp+4),
           rb2 = *(const float4*)(bp+8), rb3 = *(const float4*)(bp+12);
    #pragma unroll
    for (int it = 0; it < 4; it++) {
        cvt_store8(&As[rowt*PADK + kbt],     ra0, ra1);
        cvt_store8(&As[rowt*PADK + kbt + 8], ra2, ra3);
        cvt_store8(&Bs[rowt*PADK + kbt],     rb0, rb1);
        cvt_store8(&Bs[rowt*PADK + kbt + 8], rb2, rb3);
        __syncthreads();
        if (it < 3) {
            ap += 32; bp += 32;
            ra0 = *(const float4*)(ap);   ra1 = *(const float4*)(ap+4);
            ra2 = *(const float4*)(ap+8); ra3 = *(const float4*)(ap+12);
            rb0 = *(const float4*)(bp);   rb1 = *(const float4*)(bp+4);
            rb2 = *(const float4*)(bp+8); rb3 = *(const float4*)(bp+12);
        }
        #pragma unroll
        for (int kk = 0; kk < 32; kk += 16) {
            unsigned af[2][4], bf[4][4];
            #pragma unroll
            for (int i = 0; i < 2; i++)
                ldsm4(af[i], &As[(wm + i*16 + (lane & 15))*PADK + kk + (lane >> 4)*8]);
            #pragma unroll
            for (int j = 0; j < 4; j++)
                ldsm4(bf[j], &Bs[(wn + j*16 + (lane & 7) + ((lane >> 4) & 1)*8)*PADK
                                  + kk + ((lane >> 3) & 1)*8]);
            #pragma unroll
            for (int i = 0; i < 2; i++)
                #pragma unroll
                for (int j = 0; j < 4; j++) {
                    mma16816(acc[i][2*j],   af[i], &bf[j][0]);
                    mma16816(acc[i][2*j+1], af[i], &bf[j][2]);
                }
        }
        __syncthreads();
    }
    int r4 = lane >> 2, c2 = (lane & 3)*2;
    #pragma unroll
    for (int i = 0; i < 2; i++) {
        #pragma unroll
        for (int rs = 0; rs < 2; rs++) {
            int bl = wm + i*16 + rs*8 + r4;
            int bg = b0 + bl;
            float be2 = g_beta[bg] * 1.44269504f * g_nk[bg];
            float rsum = 0.f;
            #pragma unroll
            for (int j8 = 0; j8 < 8; j8++) {
                int ng0 = n0 + wn + j8*8 + c2;
                float v0 = fast_exp2(be2 * acc[i][j8][rs*2]   * g_nm[ng0]);
                float v1 = fast_exp2(be2 * acc[i][j8][rs*2+1] * g_nm[ng0+1]);
                *(float2*)(g_t + (size_t)bg*Nn + ng0) = make_float2(v0, v1);
                rsum += v0 + v1;
            }
            atomicAdd(&ssum[bl], rsum);
        }
    }
    __syncthreads();
    if (tid < 128) atomicAdd(&g_sum[b0 + tid], ssum[tid]);
}

// ---------------- kernel 4: head weight updates (8 floats/thread) ----------------
__global__ __launch_bounds__(256) void heads5_kernel(
    const float* __restrict__ wr, const float* __restrict__ ww,
    float* __restrict__ wr_t, float* __restrict__ ww_t)
{
    int b = blockIdx.y;
    int n = blockIdx.x * 2048 + threadIdx.x * 8;
    int lane = threadIdx.x & 31;
    float inv = 1.f / g_sum[b];
    float g = g_gate[b], omg = 1.f - g;
    float s0 = g_s[b*Ss+0], s1 = g_s[b*Ss+1], s2 = g_s[b*Ss+2];
    const float* gt = g_t + (size_t)b * Nn;

    const float* prev[5]; float* outp[5];
    prev[0] = ww + (size_t)b*Nn; outp[0] = ww_t + (size_t)b*Nn;
    #pragma unroll
    for (int hd = 1; hd < 5; hd++) {
        size_t off = ((size_t)(hd-1)*Bb + b) * Nn;
        prev[hd] = wr + off; outp[hd] = wr_t + off;
    }
    // hoist all 12 main loads
    float4 wa = *(const float4*)(gt + n);
    float4 wb = *(const float4*)(gt + n + 4);
    float4 pa[5], pb[5];
    #pragma unroll
    for (int hd = 0; hd < 5; hd++) {
        pa[hd] = *(const float4*)(prev[hd] + n);
        pb[hd] = *(const float4*)(prev[hd] + n + 4);
    }
    float wcv[10];
    wcv[1]=wa.x*inv; wcv[2]=wa.y*inv; wcv[3]=wa.z*inv; wcv[4]=wa.w*inv;
    wcv[5]=wb.x*inv; wcv[6]=wb.y*inv; wcv[7]=wb.z*inv; wcv[8]=wb.w*inv;
    wcv[0] = __shfl_up_sync(0xffffffffu, wcv[8], 1);
    wcv[9] = __shfl_down_sync(0xffffffffu, wcv[1], 1);
    float pl[5], pr[5];
    #pragma unroll
    for (int hd = 0; hd < 5; hd++) {
        pl[hd] = __shfl_up_sync(0xffffffffu, pb[hd].w, 1);
        pr[hd] = __shfl_down_sync(0xffffffffu, pa[hd].x, 1);
    }
    if (lane == 0) {
        int nl = (n - 1 + Nn) & (Nn - 1);
        wcv[0] = gt[nl] * inv;
        #pragma unroll
        for (int hd = 0; hd < 5; hd++) pl[hd] = __ldg(prev[hd] + nl);
    }
    if (lane == 31) {
        int nr = (n + 8) & (Nn - 1);
        wcv[9] = gt[nr] * inv;
        #pragma unroll
        for (int hd = 0; hd < 5; hd++) pr[hd] = __ldg(prev[hd] + nr);
    }
    #pragma unroll
    for (int hd = 0; hd < 5; hd++) {
        float pv[10];
        pv[0]=pl[hd];
        pv[1]=pa[hd].x; pv[2]=pa[hd].y; pv[3]=pa[hd].z; pv[4]=pa[hd].w;
        pv[5]=pb[hd].x; pv[6]=pb[hd].y; pv[7]=pb[hd].z; pv[8]=pb[hd].w;
        pv[9]=pr[hd];
        float wg[10];
        #pragma unroll
        for (int q = 0; q < 10; q++) wg[q] = fmaf(g, wcv[q], omg*pv[q]);
        float4 oa, ob;
        oa.x = s0*wg[2] + s1*wg[1] + s2*wg[0];
        oa.y = s0*wg[3] + s1*wg[2] + s2*wg[1];
        oa.z = s0*wg[4] + s1*wg[3] + s2*wg[2];
        oa.w = s0*wg[5] + s1*wg[4] + s2*wg[3];
        ob.x = s0*wg[6] + s1*wg[5] + s2*wg[4];
        ob.y = s0*wg[7] + s1*wg[6] + s2*wg[5];
        ob.z = s0*wg[8] + s1*wg[7] + s2*wg[6];
        ob.w = s0*wg[9] + s1*wg[8] + s2*wg[7];
        *(float4*)(outp[hd] + n)     = oa;
        *(float4*)(outp[hd] + n + 4) = ob;
    }
}

// ---------------- kernel 5: fused erase+add GEMM + m_t epilogue ----------------
__global__ __launch_bounds__(256) void memfused_hmma(
    const float* __restrict__ ww, const float* __restrict__ m, float* __restrict__ m_t)
{
    __shared__ __align__(16) __nv_bfloat16 As[32*PAD64];
    __shared__ __align__(16) __nv_bfloat16 Be[32*PADW];
    __shared__ __align__(16) __nv_bfloat16 Ba[32*PADW];
    int tid = threadIdx.x, lane = tid & 31, w = tid >> 5;
    int n0 = blockIdx.x * 64;
    int wm = (w >> 2) * 32, wn = (w & 3) * 32;
    float ae[2][4][4], aa[2][4][4];
    #pragma unroll
    for (int i = 0; i < 2; i++)
        #pragma unroll
        for (int j = 0; j < 4; j++)
            #pragma unroll
            for (int q = 0; q < 4; q++) { ae[i][j][q] = 0.f; aa[i][j][q] = 0.f; }
    int arw = tid >> 3, acl = (tid & 7) * 8;
    int brw = tid >> 3, bcl = (tid & 7) * 16;
    for (int bc = 0; bc < Bb; bc += 32) {
        const float* apw = ww + (size_t)(bc + arw)*Nn + n0 + acl;
        float4 a0 = *(const float4*)(apw), a1 = *(const float4*)(apw+4);
        cvt_store8(&As[arw*PAD64 + acl], a0, a1);
        const float* ep = g_e + (size_t)(bc + brw)*Mm + bcl;
        float4 e0 = *(const float4*)(ep),   e1 = *(const float4*)(ep+4),
               e2 = *(const float4*)(ep+8), e3 = *(const float4*)(ep+12);
        cvt_store8(&Be[brw*PADW + bcl],     e0, e1);
        cvt_store8(&Be[brw*PADW + bcl + 8], e2, e3);
        const float* apb = g_a + (size_t)(bc + brw)*Mm + bcl;
        float4 f0 = *(const float4*)(apb),   f1 = *(const float4*)(apb+4),
               f2 = *(const float4*)(apb+8), f3 = *(const float4*)(apb+12);
        cvt_store8(&Ba[brw*PADW + bcl],     f0, f1);
        cvt_store8(&Ba[brw*PADW + bcl + 8], f2, f3);
        __syncthreads();
        #pragma unroll
        for (int kk = 0; kk < 32; kk += 16) {
            unsigned af[2][4], bfe[2][4], bfa[2][4];
            #pragma unroll
            for (int i = 0; i < 2; i++)
                ldsm4t(af[i], &As[(kk + (lane & 7) + ((lane >> 4) & 1)*8)*PAD64
                                   + wm + i*16 + ((lane >> 3) & 1)*8]);
            #pragma unroll
            for (int j = 0; j < 2; j++) {
                ldsm4t(bfe[j], &Be[(kk + (lane & 15))*PADW + wn + j*16 + (lane >> 4)*8]);
                ldsm4t(bfa[j], &Ba[(kk + (lane & 15))*PADW + wn + j*16 + (lane >> 4)*8]);
            }
            #pragma unroll
            for (int i = 0; i < 2; i++)
                #pragma unroll
                for (int j = 0; j < 2; j++) {
                    mma16816(ae[i][2*j],   af[i], &bfe[j][0]);
                    mma16816(ae[i][2*j+1], af[i], &bfe[j][2]);
                    mma16816(aa[i][2*j],   af[i], &bfa[j][0]);
                    mma16816(aa[i][2*j+1], af[i], &bfa[j][2]);
                }
        }
        __syncthreads();
    }
    int r4 = lane >> 2, c2 = (lane & 3)*2;
    #pragma unroll
    for (int i = 0; i < 2; i++) {
        #pragma unroll
        for (int j8 = 0; j8 < 4; j8++) {
            int col = wn + j8*8 + c2;
            #pragma unroll
            for (int rs = 0; rs < 2; rs++) {
                int row = n0 + wm + i*16 + rs*8 + r4;
                float me0 = ae[i][j8][rs*2], me1 = ae[i][j8][rs*2+1];
                float ma0 = aa[i][j8][rs*2], ma1 = aa[i][j8][rs*2+1];
                float2 mv = *(const float2*)(m + (size_t)row*Mm + col);
                float2 o;
                o.x = mv.x * (1.f - me0) + ma0;
                o.y = mv.y * (1.f - me1) + ma1;
                *(float2*)(m_t + (size_t)row*Mm + col) = o;
            }
        }
    }
}

// ---------------- kernel 6: r_t GEMM v3 ----------------
__global__ __launch_bounds__(256, 2) void rt_hmma3(
    const float* __restrict__ wr, const float* __restrict__ m, float* __restrict__ r_out)
{
    __shared__ __align__(16) __nv_bfloat16 As[2][64*PADK];
    __shared__ __align__(16) __nv_bfloat16 Bs[2][32*PADW];
    int tid = threadIdx.x, lane = tid & 31, w = tid >> 5;
    int row0 = blockIdx.x * 64;
    int kb = blockIdx.y * 512;
    int wm = (w >> 2) * 32, wn = (w & 3) * 32;
    float acc[2][4][4];
    #pragma unroll
    for (int i = 0; i < 2; i++)
        #pragma unroll
        for (int j = 0; j < 4; j++)
            #pragma unroll
            for (int q = 0; q < 4; q++) acc[i][j][q] = 0.f;
    int arow = tid >> 2, akb = (tid & 3) * 8;
    int brow = tid >> 3, bnb = (tid & 7) * 16;
    const float* aptr = wr + (size_t)(row0 + arow)*Nn + kb + akb;
    const float* bptr = m + (size_t)(kb + brow)*Mm + bnb;
    float4 ra0 = *(const float4*)(aptr), ra1 = *(const float4*)(aptr+4);
    float4 rb0 = *(const float4*)(bptr),   rb1 = *(const float4*)(bptr+4),
           rb2 = *(const float4*)(bptr+8), rb3 = *(const float4*)(bptr+12);
    for (int it = 0; it < 16; it++) {
        __nv_bfloat16* Ab = As[it & 1];
        __nv_bfloat16* Bbf = Bs[it & 1];
        cvt_store8(&Ab[arow*PADK + akb], ra0, ra1);
        cvt_store8(&Bbf[brow*PADW + bnb],     rb0, rb1);
        cvt_store8(&Bbf[brow*PADW + bnb + 8], rb2, rb3);
        if (it < 15) {
            aptr += 32; bptr += (size_t)32 * Mm;
            ra0 = *(const float4*)(aptr); ra1 = *(const float4*)(aptr+4);
            rb0 = *(const float4*)(bptr);   rb1 = *(const float4*)(bptr+4);
            rb2 = *(const float4*)(bptr+8); rb3 = *(const float4*)(bptr+12);
        }
        __syncthreads();
        #pragma unroll
        for (int kk = 0; kk < 32; kk += 16) {
            unsigned af[2][4], bf[2][4];
            #pragma unroll
            for (int i = 0; i < 2; i++)
                ldsm4(af[i], &Ab[(wm + i*16 + (lane & 15))*PADK + kk + (lane >> 4)*8]);
            #pragma unroll
            for (int j = 0; j < 2; j++)
                ldsm4t(bf[j], &Bbf[(kk + (lane & 15))*PADW + wn + j*16 + (lane >> 4)*8]);
            #pragma unroll
            for (int i = 0; i < 2; i++)
                #pragma unroll
                for (int j = 0; j < 2; j++) {
                    mma16816(acc[i][2*j],   af[i], &bf[j][0]);
                    mma16816(acc[i][2*j+1], af[i], &bf[j][2]);
                }
        }
    }
    int r4 = lane >> 2, c2 = (lane & 3)*2;
    #pragma unroll
    for (int i = 0; i < 2; i++) {
        #pragma unroll
        for (int rs = 0; rs < 2; rs++) {
            int rb = row0 + wm + i*16 + rs*8 + r4;
            int r = rb >> 9, b = rb & (Bb - 1);
            float* dst = r_out + ((size_t)b*Rr + r)*Mm;
            #pragma unroll
            for (int j8 = 0; j8 < 4; j8++) {
                int col = wn + j8*8 + c2;
                atomicAdd(dst + col,     acc[i][j8][rs*2]);
                atomicAdd(dst + col + 1, acc[i][j8][rs*2+1]);
            }
        }
    }
}

// ---------------- streams/events ----------------
namespace {
struct HostRes {
    cudaStream_t s1, s2;
    cudaEvent_t e0, eC, eM, e1, e2;
    HostRes() {
        cudaStreamCreateWithFlags(&s1, cudaStreamNonBlocking);
        cudaStreamCreateWithFlags(&s2, cudaStreamNonBlocking);
        cudaEventCreateWithFlags(&e0, cudaEventDisableTiming);
        cudaEventCreateWithFlags(&eC, cudaEventDisableTiming);
        cudaEventCreateWithFlags(&eM, cudaEventDisableTiming);
        cudaEventCreateWithFlags(&e1, cudaEventDisableTiming);
        cudaEventCreateWithFlags(&e2, cudaEventDisableTiming);
    }
};
HostRes g_res;
}

// ---------------- launch ----------------
extern "C" void kernel_launch(void* const* d_in, const int* in_sizes, int n_in,
                              void* d_out, int out_size)
{
    const float* h_t = (const float*)d_in[0];
    const float* wr  = (const float*)d_in[1];
    const float* ww  = (const float*)d_in[2];
    const float* m   = (const float*)d_in[3];
    const float* kw  = (const float*)d_in[4];
    const float* kb  = (const float*)d_in[5];
    const float* bw  = (const float*)d_in[6];
    const float* bbv = (const float*)d_in[7];
    const float* gw  = (const float*)d_in[8];
    const float* gb  = (const float*)d_in[9];
    const float* sw  = (const float*)d_in[10];
    const float* sb  = (const float*)d_in[11];
    const float* ew  = (const float*)d_in[14];
    const float* eb  = (const float*)d_in[15];
    const float* aw  = (const float*)d_in[16];
    const float* ab  = (const float*)d_in[17];

    float* out  = (float*)d_out;
    float* r_t  = out;
    float* wr_t = out + (size_t)Bb*Rr*Mm;
    float* ww_t = wr_t + (size_t)Rr*Bb*Nn;
    float* m_t  = ww_t + (size_t)Bb*Nn;

    cudaEventRecord(g_res.e0, 0);   // root — pulls side streams into capture

    cudaStreamWaitEvent(g_res.s1, g_res.e0, 0);
    prep_m_kernel<<<2176, 256, 0, g_res.s1>>>(m, r_t);
    cudaEventRecord(g_res.eM, g_res.s1);
    rt_hmma3<<<dim3(2048/64, 32), 256, 0, g_res.s1>>>(wr, m, r_t);
    cudaEventRecord(g_res.e1, g_res.s1);

    ctrl_kernel<<<dim3(Bb/8, 8), 256>>>(h_t, kw, kb, bw, bbv, gw, gb, sw, sb, ew, eb, aw, ab);
    cudaEventRecord(g_res.eC, 0);
    prep_k_kernel<<<Bb/8, 256>>>();

    cudaStreamWaitEvent(g_res.s2, g_res.eC, 0);
    memfused_hmma<<<Nn/64, 256, 0, g_res.s2>>>(ww, m, m_t);
    cudaEventRecord(g_res.e2, g_res.s2);

    cudaStreamWaitEvent(0, g_res.eM, 0);
    sim_hmma<<<dim3(Nn/128, Bb/128), 256>>>(m);
    heads5_kernel<<<dim3(Nn/2048, Bb), 256>>>(wr, ww, wr_t, ww_t);

    cudaStreamWaitEvent(0, g_res.e1, 0);
    cudaStreamWaitEvent(0, g_res.e2, 0);
}

// round 9
// speedup vs baseline: 4.0611x; 1.1412x over previous
#include <cuda_runtime.h>
#include <cuda_bf16.h>

#define Bb 512
#define Hh 1024
#define Nn 16384
#define Mm 128
#define Rr 4
#define Ss 3

#define PADK 40
#define PADW 136
#define PAD64 72

// ---------------- scratch ----------------
__device__ __align__(16) float g_k[Bb*Mm];
__device__ __align__(16) float g_e[Bb*Mm];
__device__ __align__(16) float g_a[Bb*Mm];
__device__ float g_beta[Bb], g_gate[Bb], g_slog[Bb*Ss], g_s[Bb*Ss];
__device__ float g_nk[Bb], g_nm[Nn], g_sum[Bb];   // INVERSE norms
__device__ __align__(16) float g_t[(size_t)Bb*Nn];
__device__ __align__(16) __nv_bfloat16 g_mbf[(size_t)Nn*Mm];  // bf16 copy of m

// ---------------- helpers ----------------
__device__ __forceinline__ void ldsm4(unsigned* r, const __nv_bfloat16* p) {
    unsigned a = (unsigned)__cvta_generic_to_shared(p);
    asm volatile("ldmatrix.sync.aligned.m8n8.x4.shared.b16 {%0,%1,%2,%3}, [%4];"
        : "=r"(r[0]), "=r"(r[1]), "=r"(r[2]), "=r"(r[3]) : "r"(a));
}
__device__ __forceinline__ void ldsm4t(unsigned* r, const __nv_bfloat16* p) {
    unsigned a = (unsigned)__cvta_generic_to_shared(p);
    asm volatile("ldmatrix.sync.aligned.m8n8.x4.trans.shared.b16 {%0,%1,%2,%3}, [%4];"
        : "=r"(r[0]), "=r"(r[1]), "=r"(r[2]), "=r"(r[3]) : "r"(a));
}
__device__ __forceinline__ void mma16816(float* c, const unsigned* a, const unsigned* b) {
    asm volatile("mma.sync.aligned.m16n8k16.row.col.f32.bf16.bf16.f32 "
        "{%0,%1,%2,%3}, {%4,%5,%6,%7}, {%8,%9}, {%0,%1,%2,%3};"
        : "+f"(c[0]), "+f"(c[1]), "+f"(c[2]), "+f"(c[3])
        : "r"(a[0]), "r"(a[1]), "r"(a[2]), "r"(a[3]), "r"(b[0]), "r"(b[1]));
}
__device__ __forceinline__ void cvt_store8(__nv_bfloat16* dst, float4 v0, float4 v1) {
    __nv_bfloat162* d = (__nv_bfloat162*)dst;
    d[0] = __float22bfloat162_rn(make_float2(v0.x, v0.y));
    d[1] = __float22bfloat162_rn(make_float2(v0.z, v0.w));
    d[2] = __float22bfloat162_rn(make_float2(v1.x, v1.y));
    d[3] = __float22bfloat162_rn(make_float2(v1.z, v1.w));
}
// exp2 on the FMA pipe — no MUFU.
__device__ __forceinline__ float fast_exp2(float x) {
    float t = x + 12582912.0f;
    int ri = __float_as_int(t) - 0x4B400000;
    float f = x - (t - 12582912.0f);
    float p = 0.0013333558f;
    p = fmaf(p, f, 0.0096181298f);
    p = fmaf(p, f, 0.0555041087f);
    p = fmaf(p, f, 0.2402265070f);
    p = fmaf(p, f, 0.6931471806f);
    p = fmaf(p, f, 1.0f);
    return __int_as_float(__float_as_int(p) + (ri << 23));
}

// ---------------- kernel 1: controller projections (8x j-parallel) ----------------
__global__ __launch_bounds__(256) void ctrl_kernel(
    const float* __restrict__ h,
    const float* __restrict__ kw, const float* __restrict__ kb,
    const float* __restrict__ bw, const float* __restrict__ bbv,
    const float* __restrict__ gw, const float* __restrict__ gb,
    const float* __restrict__ sw, const float* __restrict__ sb,
    const float* __restrict__ ew, const float* __restrict__ eb,
    const float* __restrict__ aw, const float* __restrict__ ab)
{
    __shared__ float h_s[8][Hh];
    int b0 = blockIdx.x * 8;
    for (int i = threadIdx.x; i < 8*Hh; i += 256)
        h_s[i >> 10][i & 1023] = h[(size_t)(b0 + (i >> 10))*Hh + (i & 1023)];
    __syncthreads();
    int warp = threadIdx.x >> 5, lane = threadIdx.x & 31;
    for (int j = blockIdx.y*8 + warp; j < 3*Mm + 5; j += 64) {
        const float* wrow; float bias; int act;
        if (j < Mm)        { wrow = kw + (size_t)j*Hh;        bias = kb[j];      act = 0; }
        else if (j < 2*Mm) { wrow = ew + (size_t)(j-Mm)*Hh;   bias = eb[j-Mm];   act = 0; }
        else if (j < 3*Mm) { wrow = aw + (size_t)(j-2*Mm)*Hh; bias = ab[j-2*Mm]; act = 0; }
        else if (j == 384) { wrow = bw;                       bias = bbv[0];     act = 2; }
        else if (j == 385) { wrow = gw;                       bias = gb[0];      act = 0; }
        else               { wrow = sw + (size_t)(j-386)*Hh;  bias = sb[j-386];  act = 3; }
        float acc[8];
        #pragma unroll
        for (int q = 0; q < 8; q++) acc[q] = 0.f;
        for (int k = lane; k < Hh; k += 32) {
            float wv = __ldg(wrow + k);
            #pragma unroll
            for (int q = 0; q < 8; q++) acc[q] = fmaf(wv, h_s[q][k], acc[q]);
        }
        #pragma unroll
        for (int q = 0; q < 8; q++) {
            float v = acc[q];
            #pragma unroll
            for (int o = 16; o; o >>= 1) v += __shfl_down_sync(0xffffffffu, v, o);
            if (lane == 0) {
                v += bias;
                if (act == 0) v = fminf(fmaxf(v, 0.f), 1.f);
                else if (act == 2) v = fmaxf(v, 0.f);
                int b = b0 + q;
                if (j < Mm)        g_k[b*Mm + j] = v;
                else if (j < 2*Mm) g_e[b*Mm + (j-Mm)] = v;
                else if (j < 3*Mm) g_a[b*Mm + (j-2*Mm)] = v;
                else if (j == 384) g_beta[b] = v;
                else if (j == 385) g_gate[b] = v;
                else               g_slog[b*Ss + (j-386)] = v;
            }
        }
    }
}

// ---------------- kernel 2a: m inverse norms + bf16 copy + zero r_t ----------------
__global__ __launch_bounds__(256) void prep_m_kernel(const float* __restrict__ m, float* __restrict__ r_out)
{
    int warp = threadIdx.x >> 5, lane = threadIdx.x & 31;
    int bidx = blockIdx.x;
    if (bidx < 2048) {
        int n = bidx*8 + warp;
        float4 v = *(const float4*)(m + (size_t)n*Mm + lane*4);
        // bf16 copy of m
        __nv_bfloat162* dst = (__nv_bfloat162*)(g_mbf + (size_t)n*Mm + lane*4);
        dst[0] = __float22bfloat162_rn(make_float2(v.x, v.y));
        dst[1] = __float22bfloat162_rn(make_float2(v.z, v.w));
        float ss = v.x*v.x + v.y*v.y + v.z*v.z + v.w*v.w;
        #pragma unroll
        for (int o = 16; o; o >>= 1) ss += __shfl_down_sync(0xffffffffu, ss, o);
        if (lane == 0) g_nm[n] = (ss > 0.f) ? 1.f/sqrtf(ss) : 0.f;
    } else {
        int base = (bidx-2048)*2048 + threadIdx.x*8;
        float4 z = make_float4(0.f,0.f,0.f,0.f);
        *(float4*)(r_out + base)     = z;
        *(float4*)(r_out + base + 4) = z;
    }
}

// ---------------- kernel 2b: k inverse norms + shift softmax ----------------
__global__ __launch_bounds__(256) void prep_k_kernel()
{
    int warp = threadIdx.x >> 5, lane = threadIdx.x & 31;
    int b = blockIdx.x*8 + warp;
    float4 v = *(const float4*)(g_k + (size_t)b*Mm + lane*4);
    float ss = v.x*v.x + v.y*v.y + v.z*v.z + v.w*v.w;
    #pragma unroll
    for (int o = 16; o; o >>= 1) ss += __shfl_down_sync(0xffffffffu, ss, o);
    if (lane == 0) {
        g_nk[b] = (ss > 0.f) ? 1.f/sqrtf(ss) : 0.f;
        g_sum[b] = 0.f;
        float x0 = g_slog[b*Ss+0], x1 = g_slog[b*Ss+1], x2 = g_slog[b*Ss+2];
        float mx = fmaxf(x0, fmaxf(x1, x2));
        float e0 = expf(x0-mx), e1 = expf(x1-mx), e2 = expf(x2-mx);
        float it = 1.f / (e0+e1+e2);
        g_s[b*Ss+0] = e0*it; g_s[b*Ss+1] = e1*it; g_s[b*Ss+2] = e2*it;
    }
}

// ---------------- kernel 3: sim GEMM (bf16 B direct) + poly-exp2 + row sums ----------------
__global__ __launch_bounds__(256) void sim_hmma(int b_off)
{
    __shared__ __align__(16) __nv_bfloat16 As[128*PADK];
    __shared__ __align__(16) __nv_bfloat16 Bs[128*PADK];
    __shared__ float ssum[128];
    int tid = threadIdx.x, lane = tid & 31, w = tid >> 5;
    int n0 = blockIdx.x * 128, b0 = blockIdx.y * 128 + b_off;
    int wm = (w >> 1) * 32, wn = (w & 1) * 64;
    float acc[2][8][4];
    #pragma unroll
    for (int i = 0; i < 2; i++)
        #pragma unroll
        for (int j = 0; j < 8; j++)
            #pragma unroll
            for (int q = 0; q < 4; q++) acc[i][j][q] = 0.f;
    if (tid < 128) ssum[tid] = 0.f;
    int rowt = tid >> 1, kbt = (tid & 1) * 16;
    const float* ap = g_k + (size_t)(b0 + rowt)*Mm + kbt;
    const __nv_bfloat16* bp = g_mbf + (size_t)(n0 + rowt)*Mm + kbt;
    float4 ra0 = *(const float4*)(ap),   ra1 = *(const float4*)(ap+4),
           ra2 = *(const float4*)(ap+8), ra3 = *(const float4*)(ap+12);
    uint4 rb0 = *(const uint4*)(bp), rb1 = *(const uint4*)(bp+8);
    #pragma unroll
    for (int it = 0; it < 4; it++) {
        cvt_store8(&As[rowt*PADK + kbt],     ra0, ra1);
        cvt_store8(&As[rowt*PADK + kbt + 8], ra2, ra3);
        *(uint4*)(&Bs[rowt*PADK + kbt])     = rb0;
        *(uint4*)(&Bs[rowt*PADK + kbt + 8]) = rb1;
        __syncthreads();
        if (it < 3) {
            ap += 32; bp += 32;
            ra0 = *(const float4*)(ap);   ra1 = *(const float4*)(ap+4);
            ra2 = *(const float4*)(ap+8); ra3 = *(const float4*)(ap+12);
            rb0 = *(const uint4*)(bp); rb1 = *(const uint4*)(bp+8);
        }
        #pragma unroll
        for (int kk = 0; kk < 32; kk += 16) {
            unsigned af[2][4], bf[4][4];
            #pragma unroll
            for (int i = 0; i < 2; i++)
                ldsm4(af[i], &As[(wm + i*16 + (lane & 15))*PADK + kk + (lane >> 4)*8]);
            #pragma unroll
            for (int j = 0; j < 4; j++)
                ldsm4(bf[j], &Bs[(wn + j*16 + (lane & 7) + ((lane >> 4) & 1)*8)*PADK
                                  + kk + ((lane >> 3) & 1)*8]);
            #pragma unroll
            for (int i = 0; i < 2; i++)
                #pragma unroll
                for (int j = 0; j < 4; j++) {
                    mma16816(acc[i][2*j],   af[i], &bf[j][0]);
                    mma16816(acc[i][2*j+1], af[i], &bf[j][2]);
                }
        }
        __syncthreads();
    }
    int r4 = lane >> 2, c2 = (lane & 3)*2;
    #pragma unroll
    for (int i = 0; i < 2; i++) {
        #pragma unroll
        for (int rs = 0; rs < 2; rs++) {
            int bl = wm + i*16 + rs*8 + r4;
            int bg = b0 + bl;
            float be2 = g_beta[bg] * 1.44269504f * g_nk[bg];
            float rsum = 0.f;
            #pragma unroll
            for (int j8 = 0; j8 < 8; j8++) {
                int ng0 = n0 + wn + j8*8 + c2;
                float v0 = fast_exp2(be2 * acc[i][j8][rs*2]   * g_nm[ng0]);
                float v1 = fast_exp2(be2 * acc[i][j8][rs*2+1] * g_nm[ng0+1]);
                *(float2*)(g_t + (size_t)bg*Nn + ng0) = make_float2(v0, v1);
                rsum += v0 + v1;
            }
            atomicAdd(&ssum[bl], rsum);
        }
    }
    __syncthreads();
    if (tid < 128) atomicAdd(&g_sum[b0 + tid], ssum[tid]);
}

// ---------------- kernel 4: head weight updates (8 floats/thread, b-split) ----------------
__global__ __launch_bounds__(256) void heads5_kernel(
    const float* __restrict__ wr, const float* __restrict__ ww,
    float* __restrict__ wr_t, float* __restrict__ ww_t, int b_off)
{
    int b = blockIdx.y + b_off;
    int n = blockIdx.x * 2048 + threadIdx.x * 8;
    int lane = threadIdx.x & 31;
    float inv = 1.f / g_sum[b];
    float g = g_gate[b], omg = 1.f - g;
    float s0 = g_s[b*Ss+0], s1 = g_s[b*Ss+1], s2 = g_s[b*Ss+2];
    const float* gt = g_t + (size_t)b * Nn;

    const float* prev[5]; float* outp[5];
    prev[0] = ww + (size_t)b*Nn; outp[0] = ww_t + (size_t)b*Nn;
    #pragma unroll
    for (int hd = 1; hd < 5; hd++) {
        size_t off = ((size_t)(hd-1)*Bb + b) * Nn;
        prev[hd] = wr + off; outp[hd] = wr_t + off;
    }
    float4 wa = *(const float4*)(gt + n);
    float4 wb = *(const float4*)(gt + n + 4);
    float4 pa[5], pb[5];
    #pragma unroll
    for (int hd = 0; hd < 5; hd++) {
        pa[hd] = *(const float4*)(prev[hd] + n);
        pb[hd] = *(const float4*)(prev[hd] + n + 4);
    }
    float wcv[10];
    wcv[1]=wa.x*inv; wcv[2]=wa.y*inv; wcv[3]=wa.z*inv; wcv[4]=wa.w*inv;
    wcv[5]=wb.x*inv; wcv[6]=wb.y*inv; wcv[7]=wb.z*inv; wcv[8]=wb.w*inv;
    wcv[0] = __shfl_up_sync(0xffffffffu, wcv[8], 1);
    wcv[9] = __shfl_down_sync(0xffffffffu, wcv[1], 1);
    float pl[5], pr[5];
    #pragma unroll
    for (int hd = 0; hd < 5; hd++) {
        pl[hd] = __shfl_up_sync(0xffffffffu, pb[hd].w, 1);
        pr[hd] = __shfl_down_sync(0xffffffffu, pa[hd].x, 1);
    }
    if (lane == 0) {
        int nl = (n - 1 + Nn) & (Nn - 1);
        wcv[0] = gt[nl] * inv;
        #pragma unroll
        for (int hd = 0; hd < 5; hd++) pl[hd] = __ldg(prev[hd] + nl);
    }
    if (lane == 31) {
        int nr = (n + 8) & (Nn - 1);
        wcv[9] = gt[nr] * inv;
        #pragma unroll
        for (int hd = 0; hd < 5; hd++) pr[hd] = __ldg(prev[hd] + nr);
    }
    #pragma unroll
    for (int hd = 0; hd < 5; hd++) {
        float pv[10];
        pv[0]=pl[hd];
        pv[1]=pa[hd].x; pv[2]=pa[hd].y; pv[3]=pa[hd].z; pv[4]=pa[hd].w;
        pv[5]=pb[hd].x; pv[6]=pb[hd].y; pv[7]=pb[hd].z; pv[8]=pb[hd].w;
        pv[9]=pr[hd];
        float wg[10];
        #pragma unroll
        for (int q = 0; q < 10; q++) wg[q] = fmaf(g, wcv[q], omg*pv[q]);
        float4 oa, ob;
        oa.x = s0*wg[2] + s1*wg[1] + s2*wg[0];
        oa.y = s0*wg[3] + s1*wg[2] + s2*wg[1];
        oa.z = s0*wg[4] + s1*wg[3] + s2*wg[2];
        oa.w = s0*wg[5] + s1*wg[4] + s2*wg[3];
        ob.x = s0*wg[6] + s1*wg[5] + s2*wg[4];
        ob.y = s0*wg[7] + s1*wg[6] + s2*wg[5];
        ob.z = s0*wg[8] + s1*wg[7] + s2*wg[6];
        ob.w = s0*wg[9] + s1*wg[8] + s2*wg[7];
        *(float4*)(outp[hd] + n)     = oa;
        *(float4*)(outp[hd] + n + 4) = ob;
    }
}

// ---------------- kernel 5: fused erase+add GEMM + m_t epilogue ----------------
__global__ __launch_bounds__(256) void memfused_hmma(
    const float* __restrict__ ww, const float* __restrict__ m, float* __restrict__ m_t)
{
    __shared__ __align__(16) __nv_bfloat16 As[32*PAD64];
    __shared__ __align__(16) __nv_bfloat16 Be[32*PADW];
    __shared__ __align__(16) __nv_bfloat16 Ba[32*PADW];
    int tid = threadIdx.x, lane = tid & 31, w = tid >> 5;
    int n0 = blockIdx.x * 64;
    int wm = (w >> 2) * 32, wn = (w & 3) * 32;
    float ae[2][4][4], aa[2][4][4];
    #pragma unroll
    for (int i = 0; i < 2; i++)
        #pragma unroll
        for (int j = 0; j < 4; j++)
            #pragma unroll
            for (int q = 0; q < 4; q++) { ae[i][j][q] = 0.f; aa[i][j][q] = 0.f; }
    int arw = tid >> 3, acl = (tid & 7) * 8;
    int brw = tid >> 3, bcl = (tid & 7) * 16;
    for (int bc = 0; bc < Bb; bc += 32) {
        const float* apw = ww + (size_t)(bc + arw)*Nn + n0 + acl;
        float4 a0 = *(const float4*)(apw), a1 = *(const float4*)(apw+4);
        cvt_store8(&As[arw*PAD64 + acl], a0, a1);
        const float* ep = g_e + (size_t)(bc + brw)*Mm + bcl;
        float4 e0 = *(const float4*)(ep),   e1 = *(const float4*)(ep+4),
               e2 = *(const float4*)(ep+8), e3 = *(const float4*)(ep+12);
        cvt_store8(&Be[brw*PADW + bcl],     e0, e1);
        cvt_store8(&Be[brw*PADW + bcl + 8], e2, e3);
        const float* apb = g_a + (size_t)(bc + brw)*Mm + bcl;
        float4 f0 = *(const float4*)(apb),   f1 = *(const float4*)(apb+4),
               f2 = *(const float4*)(apb+8), f3 = *(const float4*)(apb+12);
        cvt_store8(&Ba[brw*PADW + bcl],     f0, f1);
        cvt_store8(&Ba[brw*PADW + bcl + 8], f2, f3);
        __syncthreads();
        #pragma unroll
        for (int kk = 0; kk < 32; kk += 16) {
            unsigned af[2][4], bfe[2][4], bfa[2][4];
            #pragma unroll
            for (int i = 0; i < 2; i++)
                ldsm4t(af[i], &As[(kk + (lane & 7) + ((lane >> 4) & 1)*8)*PAD64
                                   + wm + i*16 + ((lane >> 3) & 1)*8]);
            #pragma unroll
            for (int j = 0; j < 2; j++) {
                ldsm4t(bfe[j], &Be[(kk + (lane & 15))*PADW + wn + j*16 + (lane >> 4)*8]);
                ldsm4t(bfa[j], &Ba[(kk + (lane & 15))*PADW + wn + j*16 + (lane >> 4)*8]);
            }
            #pragma unroll
            for (int i = 0; i < 2; i++)
                #pragma unroll
                for (int j = 0; j < 2; j++) {
                    mma16816(ae[i][2*j],   af[i], &bfe[j][0]);
                    mma16816(ae[i][2*j+1], af[i], &bfe[j][2]);
                    mma16816(aa[i][2*j],   af[i], &bfa[j][0]);
                    mma16816(aa[i][2*j+1], af[i], &bfa[j][2]);
                }
        }
        __syncthreads();
    }
    int r4 = lane >> 2, c2 = (lane & 3)*2;
    #pragma unroll
    for (int i = 0; i < 2; i++) {
        #pragma unroll
        for (int j8 = 0; j8 < 4; j8++) {
            int col = wn + j8*8 + c2;
            #pragma unroll
            for (int rs = 0; rs < 2; rs++) {
                int row = n0 + wm + i*16 + rs*8 + r4;
                float me0 = ae[i][j8][rs*2], me1 = ae[i][j8][rs*2+1];
                float ma0 = aa[i][j8][rs*2], ma1 = aa[i][j8][rs*2+1];
                float2 mv = *(const float2*)(m + (size_t)row*Mm + col);
                float2 o;
                o.x = mv.x * (1.f - me0) + ma0;
                o.y = mv.y * (1.f - me1) + ma1;
                *(float2*)(m_t + (size_t)row*Mm + col) = o;
            }
        }
    }
}

// ---------------- kernel 6: r_t GEMM v4 (bf16 B direct, split-K=16, red.v2) ----------------
__global__ __launch_bounds__(256, 2) void rt_hmma4(
    const float* __restrict__ wr, float* __restrict__ r_out)
{
    __shared__ __align__(16) __nv_bfloat16 As[2][64*PADK];
    __shared__ __align__(16) __nv_bfloat16 Bs[2][32*PADW];
    int tid = threadIdx.x, lane = tid & 31, w = tid >> 5;
    int row0 = blockIdx.x * 64;
    int kb = blockIdx.y * 1024;
    int wm = (w >> 2) * 32, wn = (w & 3) * 32;
    float acc[2][4][4];
    #pragma unroll
    for (int i = 0; i < 2; i++)
        #pragma unroll
        for (int j = 0; j < 4; j++)
            #pragma unroll
            for (int q = 0; q < 4; q++) acc[i][j][q] = 0.f;
    int arow = tid >> 2, akb = (tid & 3) * 8;
    int brow = tid >> 3, bnb = (tid & 7) * 16;
    const float* aptr = wr + (size_t)(row0 + arow)*Nn + kb + akb;
    const __nv_bfloat16* bptr = g_mbf + (size_t)(kb + brow)*Mm + bnb;
    float4 ra0 = *(const float4*)(aptr), ra1 = *(const float4*)(aptr+4);
    uint4 rb0 = *(const uint4*)(bptr), rb1 = *(const uint4*)(bptr+8);
    for (int it = 0; it < 32; it++) {
        __nv_bfloat16* Ab = As[it & 1];
        __nv_bfloat16* Bbf = Bs[it & 1];
        cvt_store8(&Ab[arow*PADK + akb], ra0, ra1);
        *(uint4*)(&Bbf[brow*PADW + bnb])     = rb0;
        *(uint4*)(&Bbf[brow*PADW + bnb + 8]) = rb1;
        if (it < 31) {
            aptr += 32; bptr += (size_t)32 * Mm;
            ra0 = *(const float4*)(aptr); ra1 = *(const float4*)(aptr+4);
            rb0 = *(const uint4*)(bptr); rb1 = *(const uint4*)(bptr+8);
        }
        __syncthreads();
        #pragma unroll
        for (int kk = 0; kk < 32; kk += 16) {
            unsigned af[2][4], bf[2][4];
            #pragma unroll
            for (int i = 0; i < 2; i++)
                ldsm4(af[i], &Ab[(wm + i*16 + (lane & 15))*PADK + kk + (lane >> 4)*8]);
            #pragma unroll
            for (int j = 0; j < 2; j++)
                ldsm4t(bf[j], &Bbf[(kk + (lane & 15))*PADW + wn + j*16 + (lane >> 4)*8]);
            #pragma unroll
            for (int i = 0; i < 2; i++)
                #pragma unroll
                for (int j = 0; j < 2; j++) {
                    mma16816(acc[i][2*j],   af[i], &bf[j][0]);
                    mma16816(acc[i][2*j+1], af[i], &bf[j][2]);
                }
        }
    }
    int r4 = lane >> 2, c2 = (lane & 3)*2;
    #pragma unroll
    for (int i = 0; i < 2; i++) {
        #pragma unroll
        for (int rs = 0; rs < 2; rs++) {
            int rb = row0 + wm + i*16 + rs*8 + r4;
            int r = rb >> 9, b = rb & (Bb - 1);
            float* dst = r_out + ((size_t)b*Rr + r)*Mm;
            #pragma unroll
            for (int j8 = 0; j8 < 4; j8++) {
                int col = wn + j8*8 + c2;
                asm volatile("red.global.add.v2.f32 [%0], {%1, %2};"
                    :: "l"(dst + col), "f"(acc[i][j8][rs*2]), "f"(acc[i][j8][rs*2+1])
                    : "memory");
            }
        }
    }
}

// ---------------- streams/events ----------------
namespace {
struct HostRes {
    cudaStream_t s1, s2;
    cudaEvent_t e0, eC, eM, eS, e1, e2;
    HostRes() {
        cudaStreamCreateWithFlags(&s1, cudaStreamNonBlocking);
        cudaStreamCreateWithFlags(&s2, cudaStreamNonBlocking);
        cudaEventCreateWithFlags(&e0, cudaEventDisableTiming);
        cudaEventCreateWithFlags(&eC, cudaEventDisableTiming);
        cudaEventCreateWithFlags(&eM, cudaEventDisableTiming);
        cudaEventCreateWithFlags(&eS, cudaEventDisableTiming);
        cudaEventCreateWithFlags(&e1, cudaEventDisableTiming);
        cudaEventCreateWithFlags(&e2, cudaEventDisableTiming);
    }
};
HostRes g_res;
}

// ---------------- launch ----------------
extern "C" void kernel_launch(void* const* d_in, const int* in_sizes, int n_in,
                              void* d_out, int out_size)
{
    const float* h_t = (const float*)d_in[0];
    const float* wr  = (const float*)d_in[1];
    const float* ww  = (const float*)d_in[2];
    const float* m   = (const float*)d_in[3];
    const float* kw  = (const float*)d_in[4];
    const float* kb  = (const float*)d_in[5];
    const float* bw  = (const float*)d_in[6];
    const float* bbv = (const float*)d_in[7];
    const float* gw  = (const float*)d_in[8];
    const float* gb  = (const float*)d_in[9];
    const float* sw  = (const float*)d_in[10];
    const float* sb  = (const float*)d_in[11];
    const float* ew  = (const float*)d_in[14];
    const float* eb  = (const float*)d_in[15];
    const float* aw  = (const float*)d_in[16];
    const float* ab  = (const float*)d_in[17];

    float* out  = (float*)d_out;
    float* r_t  = out;
    float* wr_t = out + (size_t)Bb*Rr*Mm;
    float* ww_t = wr_t + (size_t)Rr*Bb*Nn;
    float* m_t  = ww_t + (size_t)Bb*Nn;

    cudaEventRecord(g_res.e0, 0);   // root — pulls side streams into capture

    // s1: prep_m (m norms + bf16 copy + zero r_t) -> rt GEMM
    cudaStreamWaitEvent(g_res.s1, g_res.e0, 0);
    prep_m_kernel<<<2176, 256, 0, g_res.s1>>>(m, r_t);
    cudaEventRecord(g_res.eM, g_res.s1);
    rt_hmma4<<<dim3(2048/64, 16), 256, 0, g_res.s1>>>(wr, r_t);
    cudaEventRecord(g_res.e1, g_res.s1);

    // legacy: ctrl -> prep_k
    ctrl_kernel<<<dim3(Bb/8, 8), 256>>>(h_t, kw, kb, bw, bbv, gw, gb, sw, sb, ew, eb, aw, ab);
    cudaEventRecord(g_res.eC, 0);
    prep_k_kernel<<<Bb/8, 256>>>();

    // s2: memfused after ctrl
    cudaStreamWaitEvent(g_res.s2, g_res.eC, 0);
    memfused_hmma<<<Nn/64, 256, 0, g_res.s2>>>(ww, m, m_t);

    // legacy: sim halves (needs prep_k + prep_m)
    cudaStreamWaitEvent(0, g_res.eM, 0);
    sim_hmma<<<dim3(Nn/128, 2), 256>>>(0);          // b 0..255
    cudaEventRecord(g_res.eS, 0);
    sim_hmma<<<dim3(Nn/128, 2), 256>>>(256);        // b 256..511

    // s2: heads half A overlaps sim half B
    cudaStreamWaitEvent(g_res.s2, g_res.eS, 0);
    heads5_kernel<<<dim3(Nn/2048, 256), 256, 0, g_res.s2>>>(wr, ww, wr_t, ww_t, 0);
    cudaEventRecord(g_res.e2, g_res.s2);

    // legacy: heads half B
    heads5_kernel<<<dim3(Nn/2048, 256), 256>>>(wr, ww, wr_t, ww_t, 256);

    cudaStreamWaitEvent(0, g_res.e1, 0);
    cudaStreamWaitEvent(0, g_res.e2, 0);
}